// round 13
// baseline (speedup 1.0000x reference)
#include <cuda_runtime.h>
#include <cuda_bf16.h>
#include <cuda_fp8.h>
#include <math.h>
#include <stdint.h>

// ---------------- problem constants (fixed shapes from setup_inputs) -------
#define EDIM   512
#define HN     8
#define HD     64
#define FFD    2048
#define NB     8      // batch
#define QLEN   30
#define DLEN   2000
#define CHUNK_ 40
#define OVL    5
#define EXTL   50
#define CPD    50     // chunks per doc
#define NCH    400    // NB*CPD chunk sequences
#define SCH    50     // chunk seq len
#define QBASE  20000  // NCH*SCH
#define NTOK   20240  // QBASE + NB*QLEN
#define NSEQ   408
#define WN     986
#define NKN    11
#define SLIDEH 15

#define FSTR   80     // smem row stride in BYTES (fp8)
#define WSCL     64.0f
#define WSCL_INV 0.015625f
#define PERK_POS 284  // positions staged per perk block (2*127+30)
#define GPERS  296    // persistent GEMM grid (2 CTAs/SM x 148 SMs)

// ---------------- scratch (device globals; no allocation at runtime) -------
__device__ float g_seq [NTOK*EDIM];
__device__ float g_tmask[NTOK];
__device__ float g_qn  [NB*QLEN*EDIM];
__device__ float g_dn  [NB*DLEN*EDIM];
__device__ float g_valid[NB*DLEN];
__device__ float g_wvalid[NB*WN];
__device__ float g_perk[NB*WN*NKN];
// bf16 intermediates
__device__ __nv_bfloat16 g_xb  [NTOK*EDIM];      // residual stream
__device__ __nv_bfloat16 g_x1b [NTOK*EDIM];      // residual stream (mid)
__device__ __nv_bfloat16 g_qkvh[NTOK*3*EDIM];
__device__ __nv_bfloat16 g_projh[2L*NTOK*EDIM];  // split-K partials
__device__ __nv_bfloat16 g_acts[(long)NB*QLEN*NKN*DLEN];
// fp8 activation / weight copies (e4m3 raw bytes)
__device__ uint8_t g_xh  [NTOK*EDIM];
__device__ uint8_t g_x1h [NTOK*EDIM];
__device__ uint8_t g_atth[NTOK*EDIM];
__device__ uint8_t g_ffh [NTOK*FFD];
__device__ uint8_t g_wqkvh[2*3*EDIM*EDIM];
__device__ uint8_t g_woh  [2*EDIM*EDIM];
__device__ uint8_t g_wff1h[2*FFD*EDIM];
__device__ uint8_t g_wff2h[2*EDIM*FFD];

// ---------------- helpers ---------------------------------------------------
__device__ __forceinline__ float blockSum128(float v) {
    __shared__ float sh[4];
#pragma unroll
    for (int o = 16; o > 0; o >>= 1) v += __shfl_xor_sync(0xffffffffu, v, o);
    if ((threadIdx.x & 31) == 0) sh[threadIdx.x >> 5] = v;
    __syncthreads();
    float t = sh[0] + sh[1] + sh[2] + sh[3];
    __syncthreads();
    return t;
}
__device__ __forceinline__ uint8_t f2fp8(float x) {
    return (uint8_t)__nv_cvt_float_to_fp8(x, __NV_SATFINITE, __NV_E4M3);
}
__device__ __forceinline__ uint16_t pack2fp8(float lo, float hi) {
    uint16_t r;
    asm("cvt.rn.satfinite.e4m3x2.f32 %0, %1, %2;" : "=h"(r) : "f"(hi), "f"(lo));
    return r;
}
__device__ __forceinline__ void cpasync16s(uint32_t saddr, const void* gmem, bool pred) {
    int sz = pred ? 16 : 0;
    asm volatile("cp.async.cg.shared.global [%0], [%1], 16, %2;\n"
                 :: "r"(saddr), "l"(gmem), "r"(sz));
}
__device__ __forceinline__ void mma_fp8(float* d, const uint32_t* a, const uint32_t* b) {
    asm volatile(
        "mma.sync.aligned.m16n8k32.row.col.f32.e4m3.e4m3.f32 "
        "{%0,%1,%2,%3}, {%4,%5,%6,%7}, {%8,%9}, {%0,%1,%2,%3};\n"
        : "+f"(d[0]), "+f"(d[1]), "+f"(d[2]), "+f"(d[3])
        : "r"(a[0]), "r"(a[1]), "r"(a[2]), "r"(a[3]), "r"(b[0]), "r"(b[1]));
}
__device__ __forceinline__ void ldmx4(uint32_t* r, uint32_t saddr) {
    asm volatile("ldmatrix.sync.aligned.m8n8.x4.shared.b16 {%0,%1,%2,%3}, [%4];"
                 : "=r"(r[0]), "=r"(r[1]), "=r"(r[2]), "=r"(r[3]) : "r"(saddr));
}

// ---------------- fp32 -> fp8 conversion, all 4 weight tensors in one launch
__global__ void k_tofp8_all(const float* __restrict__ s0, uint8_t* __restrict__ d0,
                            const float* __restrict__ s1, uint8_t* __restrict__ d1,
                            const float* __restrict__ s2, uint8_t* __restrict__ d2,
                            const float* __restrict__ s3, uint8_t* __restrict__ d3) {
    int blk = blockIdx.x;
    const float* src; uint8_t* dst; long base;
    if (blk < 1536)      { src = s0; dst = d0; base = (long)blk * 1024; }
    else if (blk < 2048) { src = s1; dst = d1; base = (long)(blk - 1536) * 1024; }
    else if (blk < 4096) { src = s2; dst = d2; base = (long)(blk - 2048) * 1024; }
    else                 { src = s3; dst = d3; base = (long)(blk - 4096) * 1024; }
    long i = base + (long)threadIdx.x * 4;
    float4 v = *(const float4*)(src + i);
    uint32_t pk = (uint32_t)pack2fp8(v.x * WSCL, v.y * WSCL)
                | ((uint32_t)pack2fp8(v.z * WSCL, v.w * WSCL) << 16);
    *(uint32_t*)(dst + i) = pk;
}

// ---------------- setup: gather chunked docs + queries, add pos ------------
__global__ void k_setup(const float* __restrict__ qe, const float* __restrict__ de,
                        const float* __restrict__ qm, const float* __restrict__ dm,
                        const float* __restrict__ pq, const float* __restrict__ pd) {
    long gid = (long)blockIdx.x * 256 + threadIdx.x;
    if (gid >= (long)NTOK * EDIM) return;
    int tok = (int)(gid >> 9);
    int e = (int)(gid & 511);
    float val, pos, mk;
    if (tok < QBASE) {
        int s = tok / SCH, t = tok % SCH;
        int b = s / CPD, c = s % CPD;
        int j = c * CHUNK_ + t - OVL;
        if (j >= 0 && j < DLEN) {
            val = de[((long)(b * DLEN + j)) * EDIM + e];
            mk  = dm[b * DLEN + j];
        } else { val = 0.f; mk = 0.f; }
        pos = pd[t * EDIM + e];
    } else {
        int i2 = tok - QBASE; int b = i2 / QLEN, t = i2 % QLEN;
        val = qe[((long)(b * QLEN + t)) * EDIM + e];
        mk  = qm[b * QLEN + t];
        pos = pq[t * EDIM + e];
    }
    g_seq[gid] = val;
    float xv = val + pos;
    g_xb[gid] = __float2bfloat16(xv);
    g_xh[gid] = f2fp8(xv);
    if (e == 0) g_tmask[tok] = mk;
}

// ---------------- persistent fp8 tensor-core GEMM ---------------------------
// C[M,N] = A[M,K]@B[N,K]^T. 128x128 tile, BK=64, 256 threads, warp tile 64x32,
// m16n8k32 e4m3 mma, ldmatrix.x4, double-buffered cp.async. Persistent CTAs:
// each block loops over tiles t = bid, bid+G, ... with t -> (z,y,x).
__global__ void __launch_bounds__(256, 2) k_gemm_fp8(
    const uint8_t* __restrict__ A, const uint8_t* __restrict__ B,
    const float* __restrict__ Bias, __nv_bfloat16* __restrict__ C16,
    uint8_t* __restrict__ C8, int M, int N, int K, int relu, long zoff,
    int nx, int ny, int nz)
{
    __shared__ uint8_t As[2][128 * FSTR];
    __shared__ uint8_t Bs[2][128 * FSTR];
    int tid = threadIdx.x;
    int warp = tid >> 5, lane = tid & 31;
    int wm = (warp >> 2) * 64, wn = (warp & 3) * 32;
    int gid = lane >> 2, tig = lane & 3;
    int row = tid >> 2;
    int q   = tid & 3;
    int Keff = K / nz;
    int nk = Keff >> 6;
    int nxy = nx * ny;
    int ntile = nxy * nz;

    // tile-invariant smem addresses
    uint32_t sA[2][2], sB[2][2];
#pragma unroll
    for (int i = 0; i < 2; i++) {
        int r = row + i * 64;
#pragma unroll
        for (int b = 0; b < 2; b++) {
            sA[b][i] = (uint32_t)__cvta_generic_to_shared(&As[b][r * FSTR + q * 16]);
            sB[b][i] = (uint32_t)__cvta_generic_to_shared(&Bs[b][r * FSTR + q * 16]);
        }
    }
    int l8 = lane & 7;
    uint32_t aBase[2], bBase[2];
    {
        int aRow = wm + l8 + ((lane & 8) ? 8 : 0);
        uint32_t aOff = (uint32_t)(aRow * FSTR) + ((lane & 16) ? 16u : 0u);
        int bRow = wn + l8 + ((lane & 16) ? 8 : 0);
        uint32_t bOff = (uint32_t)(bRow * FSTR) + ((lane & 8) ? 16u : 0u);
#pragma unroll
        for (int b = 0; b < 2; b++) {
            aBase[b] = (uint32_t)__cvta_generic_to_shared(&As[b][0]) + aOff;
            bBase[b] = (uint32_t)__cvta_generic_to_shared(&Bs[b][0]) + bOff;
        }
    }

    for (int t = blockIdx.x; t < ntile; t += gridDim.x) {
        int z = t / nxy;
        int r2 = t - z * nxy;
        int tyy = r2 / nx;
        int txx = r2 - tyy * nx;
        int m0 = tyy * 128, n0 = txx * 128;
        int kbeg = z * Keff;
        const float* Biasz = (z == 0) ? Bias : nullptr;
        __nv_bfloat16* C16z = C16 ? (C16 + (z ? zoff : 0)) : nullptr;

        float acc[4][4][4];
#pragma unroll
        for (int i = 0; i < 4; i++)
#pragma unroll
            for (int j = 0; j < 4; j++)
#pragma unroll
                for (int r = 0; r < 4; r++) acc[i][j][r] = 0.f;

        bool pm[2], pn[2];
        const uint8_t* aP[2];
        const uint8_t* bP[2];
#pragma unroll
        for (int i = 0; i < 2; i++) {
            int r = row + i * 64;
            int gm = m0 + r; pm[i] = gm < M; int gmr = pm[i] ? gm : (M - 1);
            int gn = n0 + r; pn[i] = gn < N; int gnr = pn[i] ? gn : (N - 1);
            aP[i] = A + (long)gmr * K + kbeg + q * 16;
            bP[i] = B + (long)gnr * K + kbeg + q * 16;
        }

        {   // prologue: tile 0 -> buf 0
#pragma unroll
            for (int i = 0; i < 2; i++) {
                cpasync16s(sA[0][i], aP[i], pm[i]);
                cpasync16s(sB[0][i], bP[i], pn[i]);
                aP[i] += 64; bP[i] += 64;
            }
            asm volatile("cp.async.commit_group;\n");
        }

        int buf = 0;
        for (int kt = 0; kt < nk; kt++) {
            asm volatile("cp.async.wait_group 0;\n");
            __syncthreads();
            if (kt + 1 < nk) {
                int nb = buf ^ 1;
#pragma unroll
                for (int i = 0; i < 2; i++) {
                    cpasync16s(sA[nb][i], aP[i], pm[i]);
                    cpasync16s(sB[nb][i], bP[i], pn[i]);
                    aP[i] += 64; bP[i] += 64;
                }
                asm volatile("cp.async.commit_group;\n");
            }
#pragma unroll
            for (int ks = 0; ks < 2; ks++) {
                uint32_t koff = (uint32_t)(ks * 32);
                uint32_t af[4][4], bfr[2][4];
#pragma unroll
                for (int mi = 0; mi < 4; mi++)
                    ldmx4(af[mi], aBase[buf] + koff + (uint32_t)(mi * 16 * FSTR));
                ldmx4(bfr[0], bBase[buf] + koff);
                ldmx4(bfr[1], bBase[buf] + koff + (uint32_t)(16 * FSTR));
#pragma unroll
                for (int mi = 0; mi < 4; mi++)
#pragma unroll
                    for (int ni = 0; ni < 4; ni++)
                        mma_fp8(acc[mi][ni], af[mi], &bfr[ni >> 1][(ni & 1) * 2]);
            }
            buf ^= 1;
            __syncthreads();
        }

#pragma unroll
        for (int mi = 0; mi < 4; mi++) {
            int r0 = m0 + wm + mi * 16 + gid;
            int r1 = r0 + 8;
#pragma unroll
            for (int ni = 0; ni < 4; ni++) {
                int cb = n0 + wn + ni * 8 + 2 * tig;
                float b0 = Biasz ? Biasz[cb] : 0.f;
                float b1 = Biasz ? Biasz[cb + 1] : 0.f;
                float v0 = acc[mi][ni][0] * WSCL_INV + b0, v1 = acc[mi][ni][1] * WSCL_INV + b1;
                float v2 = acc[mi][ni][2] * WSCL_INV + b0, v3 = acc[mi][ni][3] * WSCL_INV + b1;
                if (relu) { v0 = fmaxf(v0, 0.f); v1 = fmaxf(v1, 0.f);
                            v2 = fmaxf(v2, 0.f); v3 = fmaxf(v3, 0.f); }
                if (C16z) {
                    if (r0 < M) *(__nv_bfloat162*)(C16z + (long)r0 * N + cb) = __floats2bfloat162_rn(v0, v1);
                    if (r1 < M) *(__nv_bfloat162*)(C16z + (long)r1 * N + cb) = __floats2bfloat162_rn(v2, v3);
                }
                if (C8) {
                    if (r0 < M) *(uint16_t*)(C8 + (long)r0 * N + cb) = pack2fp8(v0, v1);
                    if (r1 < M) *(uint16_t*)(C8 + (long)r1 * N + cb) = pack2fp8(v2, v3);
                }
            }
        }
    }
}

// ---------------- fused cos GEMM + RBF acts ----------------------------------
// cos[b,q,d] = qn[b,q,:]·dn[b,d,:]; acts written directly as packed bf16.
__global__ void __launch_bounds__(128) k_cos_acts(
    const float* __restrict__ mup, const float* __restrict__ sgp)
{
    __shared__ float As[16][32];
    __shared__ float Bs[16][260];
    __shared__ float mu[NKN], i2s[NKN];
    int b = blockIdx.z;
    int n0 = blockIdx.x * 256;
    const float* A = g_qn + (long)b * QLEN * EDIM;
    const float* B = g_dn + (long)b * DLEN * EDIM;
    int tid = threadIdx.x;
    if (tid < NKN) {
        mu[tid] = mup[tid];
        float sg = sgp[tid];
        i2s[tid] = 1.f / (2.f * sg * sg);
    }
    int ty = tid >> 5, tx = tid & 31;
    float acc[8][8];
#pragma unroll
    for (int i = 0; i < 8; i++)
#pragma unroll
        for (int j = 0; j < 8; j++) acc[i][j] = 0.f;

    for (int k0 = 0; k0 < EDIM; k0 += 16) {
        {
            int r = tid >> 2, c = (tid & 3) << 2;
            float4 v = make_float4(0.f, 0.f, 0.f, 0.f);
            if (r < QLEN) v = *(const float4*)(A + (long)r * EDIM + k0 + c);
            As[c + 0][r] = v.x; As[c + 1][r] = v.y; As[c + 2][r] = v.z; As[c + 3][r] = v.w;
        }
#pragma unroll
        for (int j = 0; j < 8; j++) {
            int idx = tid + 128 * j;
            int r = idx >> 2, c = (idx & 3) << 2;
            int gn = n0 + r;
            float4 v = make_float4(0.f, 0.f, 0.f, 0.f);
            if (gn < DLEN) v = *(const float4*)(B + (long)gn * EDIM + k0 + c);
            Bs[c + 0][r] = v.x; Bs[c + 1][r] = v.y; Bs[c + 2][r] = v.z; Bs[c + 3][r] = v.w;
        }
        __syncthreads();
#pragma unroll
        for (int kk = 0; kk < 16; kk++) {
            float a[8], bb[8];
            *(float4*)(a)      = *(const float4*)(&As[kk][ty * 8]);
            *(float4*)(a + 4)  = *(const float4*)(&As[kk][ty * 8 + 4]);
            *(float4*)(bb)     = *(const float4*)(&Bs[kk][tx * 8]);
            *(float4*)(bb + 4) = *(const float4*)(&Bs[kk][tx * 8 + 4]);
#pragma unroll
            for (int i = 0; i < 8; i++)
#pragma unroll
                for (int j = 0; j < 8; j++) acc[i][j] = fmaf(a[i], bb[j], acc[i][j]);
        }
        __syncthreads();
    }
    // epilogue: RBF kernels + mask, packed bf16 stores (16B per (row,k))
    int p8 = n0 + tx * 8;
    float vd[8];
#pragma unroll
    for (int j = 0; j < 8; j++) {
        int p = p8 + j;
        vd[j] = (p < DLEN) ? g_valid[b * DLEN + p] : 0.f;
    }
    bool full = (p8 + 8 <= DLEN);
#pragma unroll
    for (int i = 0; i < 8; i++) {
        int m = ty * 8 + i;
        if (m >= QLEN) continue;
        long rowbase = ((long)(b * QLEN + m)) * NKN;
#pragma unroll
        for (int k = 0; k < NKN; k++) {
            __align__(16) __nv_bfloat16 tmp[8];
#pragma unroll
            for (int j = 0; j < 8; j++) {
                float d = acc[i][j] - mu[k];
                tmp[j] = __float2bfloat16(__expf(-d * d * i2s[k]) * vd[j]);
            }
            __nv_bfloat16* addr = g_acts + (rowbase + k) * DLEN + p8;
            if (full) *(uint4*)addr = *(uint4*)tmp;
            else {
                for (int j = 0; j < 8 && p8 + j < DLEN; j++) addr[j] = tmp[j];
            }
        }
    }
}

// ---------------- attention: one block per (sequence, head), 2-row unroll --
__global__ void __launch_bounds__(128) k_attn() {
    int bid = blockIdx.x;
    int s = bid >> 3, h = bid & 7;
    int S, base;
    if (s < NCH) { S = SCH; base = s * SCH; }
    else         { S = QLEN; base = QBASE + (s - NCH) * QLEN; }
    __shared__ float Qs[SCH * HD];
    __shared__ float Kt[HD * 52];
    __shared__ float Vs[SCH * HD];
    __shared__ float mk[52];
    __shared__ float Pw[4][2][52];
    int tid = threadIdx.x;
    for (int idx = tid; idx < S * HD; idx += 128) {
        int r = idx >> 6, d = idx & 63;
        const __nv_bfloat16* row = g_qkvh + (long)(base + r) * (3 * EDIM) + h * HD;
        Qs[idx]        = __bfloat162float(row[d]);
        Kt[d * 52 + r] = __bfloat162float(row[EDIM + d]);
        Vs[idx]        = __bfloat162float(row[2 * EDIM + d]);
    }
    if (tid < S) mk[tid] = g_tmask[base + tid];
    __syncthreads();
    int warp = tid >> 5, lane = tid & 31;
    int j0 = lane, j1 = lane + 32;
    bool v0ok = j0 < S, v1ok;
    for (int i = warp; i < S; i += 8) {
        int ib = i + 4;
        bool has2 = ib < S;
        int ibc = has2 ? ib : i;
        float s0a = -1e30f, s1a = -1e30f, s0b = -1e30f, s1b = -1e30f;
        v1ok = j1 < S;
        if (v0ok) {
            float aa = 0.f, ab = 0.f;
#pragma unroll
            for (int d = 0; d < HD; d++) {
                float kv = Kt[d * 52 + j0];
                aa = fmaf(Qs[i * HD + d], kv, aa);
                ab = fmaf(Qs[ibc * HD + d], kv, ab);
            }
            s0a = (mk[j0] > 0.f) ? aa * 0.125f : -1e9f;
            s0b = (mk[j0] > 0.f) ? ab * 0.125f : -1e9f;
        }
        if (v1ok) {
            float aa = 0.f, ab = 0.f;
#pragma unroll
            for (int d = 0; d < HD; d++) {
                float kv = Kt[d * 52 + j1];
                aa = fmaf(Qs[i * HD + d], kv, aa);
                ab = fmaf(Qs[ibc * HD + d], kv, ab);
            }
            s1a = (mk[j1] > 0.f) ? aa * 0.125f : -1e9f;
            s1b = (mk[j1] > 0.f) ? ab * 0.125f : -1e9f;
        }
        float ma = fmaxf(s0a, s1a);
#pragma unroll
        for (int o = 16; o > 0; o >>= 1) ma = fmaxf(ma, __shfl_xor_sync(0xffffffffu, ma, o));
        float e0a = v0ok ? __expf(s0a - ma) : 0.f;
        float e1a = v1ok ? __expf(s1a - ma) : 0.f;
        float za = e0a + e1a;
#pragma unroll
        for (int o = 16; o > 0; o >>= 1) za += __shfl_xor_sync(0xffffffffu, za, o);
        float inva = 1.f / za;
        if (v0ok) Pw[warp][0][j0] = e0a * inva;
        if (v1ok) Pw[warp][0][j1] = e1a * inva;
        float mb = fmaxf(s0b, s1b);
#pragma unroll
        for (int o = 16; o > 0; o >>= 1) mb = fmaxf(mb, __shfl_xor_sync(0xffffffffu, mb, o));
        float e0b = v0ok ? __expf(s0b - mb) : 0.f;
        float e1b = v1ok ? __expf(s1b - mb) : 0.f;
        float zb = e0b + e1b;
#pragma unroll
        for (int o = 16; o > 0; o >>= 1) zb += __shfl_xor_sync(0xffffffffu, zb, o);
        float invb = 1.f / zb;
        if (v0ok) Pw[warp][1][j0] = e0b * invb;
        if (v1ok) Pw[warp][1][j1] = e1b * invb;
        __syncwarp();
        float o0a = 0.f, o1a = 0.f, o0b = 0.f, o1b = 0.f;
        for (int j = 0; j < S; j++) {
            float pa = Pw[warp][0][j];
            float pb = Pw[warp][1][j];
            float v0 = Vs[j * HD + lane];
            float v1 = Vs[j * HD + lane + 32];
            o0a = fmaf(pa, v0, o0a); o1a = fmaf(pa, v1, o1a);
            o0b = fmaf(pb, v0, o0b); o1b = fmaf(pb, v1, o1b);
        }
        long orow = (long)(base + i) * EDIM + h * HD;
        g_atth[orow + lane]      = f2fp8(o0a);
        g_atth[orow + lane + 32] = f2fp8(o1a);
        if (has2) {
            long orow2 = (long)(base + ib) * EDIM + h * HD;
            g_atth[orow2 + lane]      = f2fp8(o0b);
            g_atth[orow2 + lane + 32] = f2fp8(o1b);
        }
        __syncwarp();
    }
}

// ---------------- residual-add + layernorm ----------------------------------
// finalflag=0: store bf16 + fp8 copies. finalflag=1 (last LN): fuse repnorm.
__global__ void __launch_bounds__(128) k_addln(
    const __nv_bfloat16* __restrict__ X, const __nv_bfloat16* __restrict__ Y,
    const __nv_bfloat16* __restrict__ Y2,
    const float* __restrict__ G, const float* __restrict__ Bv,
    __nv_bfloat16* __restrict__ Out, uint8_t* __restrict__ OutH,
    const float* __restrict__ mixer, int finalflag)
{
    long tok = blockIdx.x;
    int t = threadIdx.x;
    float* dst = nullptr;
    if (finalflag) {
        int tokc = (int)tok;
        if (tokc < QBASE) {
            int s = tokc / SCH, tt = tokc % SCH;
            int tl = tt - OVL;
            if (tl < 0 || tl >= CHUNK_) return;
            int b = s / CPD, c = s % CPD;
            dst = g_dn + ((long)(b * DLEN + c * CHUNK_ + tl)) * EDIM;
        } else {
            dst = g_qn + (long)(tokc - QBASE) * EDIM;
        }
    }
    __nv_bfloat162 x0 = *(const __nv_bfloat162*)(X + tok * EDIM + t * 4);
    __nv_bfloat162 x1 = *(const __nv_bfloat162*)(X + tok * EDIM + t * 4 + 2);
    __nv_bfloat162 y0 = *(const __nv_bfloat162*)(Y + tok * EDIM + t * 4);
    __nv_bfloat162 y1 = *(const __nv_bfloat162*)(Y + tok * EDIM + t * 4 + 2);
    __nv_bfloat162 z0 = *(const __nv_bfloat162*)(Y2 + tok * EDIM + t * 4);
    __nv_bfloat162 z1 = *(const __nv_bfloat162*)(Y2 + tok * EDIM + t * 4 + 2);
    float4 v = make_float4(
        __bfloat162float(x0.x) + __bfloat162float(y0.x) + __bfloat162float(z0.x),
        __bfloat162float(x0.y) + __bfloat162float(y0.y) + __bfloat162float(z0.y),
        __bfloat162float(x1.x) + __bfloat162float(y1.x) + __bfloat162float(z1.x),
        __bfloat162float(x1.y) + __bfloat162float(y1.y) + __bfloat162float(z1.y));
    float s = blockSum128(v.x + v.y + v.z + v.w);
    float mean = s * (1.f / 512.f);
    float dx = v.x - mean, dy = v.y - mean, dz = v.z - mean, dw = v.w - mean;
    float sq = blockSum128(dx * dx + dy * dy + dz * dz + dw * dw);
    float rstd = rsqrtf(sq * (1.f / 512.f) + 1e-5f);
    float4 g = ((const float4*)G)[t], bb = ((const float4*)Bv)[t];
    float4 o = make_float4(dx * rstd * g.x + bb.x, dy * rstd * g.y + bb.y,
                           dz * rstd * g.z + bb.z, dw * rstd * g.w + bb.w);
    if (!finalflag) {
        *(__nv_bfloat162*)(Out + tok * EDIM + t * 4)     = __floats2bfloat162_rn(o.x, o.y);
        *(__nv_bfloat162*)(Out + tok * EDIM + t * 4 + 2) = __floats2bfloat162_rn(o.z, o.w);
        uint32_t pk = (uint32_t)pack2fp8(o.x, o.y) | ((uint32_t)pack2fp8(o.z, o.w) << 16);
        *(uint32_t*)(OutH + tok * EDIM + t * 4) = pk;
        return;
    }
    float mx = mixer[0];
    float mkv = g_tmask[tok];
    float4 sv = ((const float4*)(g_seq + tok * EDIM))[t];
    float4 r = make_float4((mx * sv.x + (1.f - mx) * o.x) * mkv,
                           (mx * sv.y + (1.f - mx) * o.y) * mkv,
                           (mx * sv.z + (1.f - mx) * o.z) * mkv,
                           (mx * sv.w + (1.f - mx) * o.w) * mkv);
    float sq2 = blockSum128(r.x * r.x + r.y * r.y + r.z * r.z + r.w * r.w);
    float inv = 1.f / (sqrtf(sq2) + 1e-13f);
    ((float4*)dst)[t] = make_float4(r.x * inv, r.y * inv, r.z * inv, r.w * inv);
}

// ---------------- per-position validity (m_in * packed) --------------------
__global__ void k_valid(const float* __restrict__ dm) {
    int gid = blockIdx.x * 256 + threadIdx.x;
    if (gid >= NB * DLEN) return;
    int b = gid / DLEN, p = gid % DLEN;
    int c = p / CHUNK_;
    float s = 0.f;
    for (int d = 0; d < CHUNK_; d++) s += dm[b * DLEN + c * CHUNK_ + d];
    float packed = (s != 0.f) ? 1.f : 0.f;
    g_valid[gid] = dm[b * DLEN + p] * packed;
}

// ---------------- window validity -------------------------------------------
__global__ void k_wvalid() {
    int gid = blockIdx.x * 256 + threadIdx.x;
    if (gid >= NB * WN) return;
    int b = gid / WN, w = gid % WN;
    float any = 0.f;
    for (int i = 0; i < 30; i++)
        if (g_valid[b * DLEN + 2 * w + i] != 0.f) any = 1.f;
    g_wvalid[gid] = any;
}

// ---------------- per-kernel window log-saturation (smem-staged, bf16 src) --
__global__ void __launch_bounds__(128) k_perk(const float* __restrict__ qm) {
    __shared__ float sa[QLEN][PERK_POS];
    __shared__ float qms[QLEN];
    int wt = blockIdx.x, k = blockIdx.y, b = blockIdx.z;
    int w0 = wt * 128;
    int p0 = 2 * w0;
    int npos = DLEN - p0; if (npos > PERK_POS) npos = PERK_POS;
    int tid = threadIdx.x;
    for (int idx = tid; idx < QLEN * npos; idx += 128) {
        int q = idx / npos, j = idx % npos;
        sa[q][j] = __bfloat162float(
            g_acts[(((long)(b * QLEN + q)) * NKN + k) * DLEN + p0 + j]);
    }
    if (tid < QLEN) qms[tid] = qm[b * QLEN + tid];
    __syncthreads();
    int w = w0 + tid;
    if (w >= WN) return;
    float wv = g_wvalid[b * WN + w];
    float ssum = 0.f;
    if (wv != 0.f) {
        int off = 2 * tid;
        for (int q = 0; q < QLEN; q++) {
            float pkq = 0.f;
#pragma unroll
            for (int i = 0; i < 30; i++) pkq += sa[q][off + i];
            ssum += qms[q] * logf(fmaxf(pkq, 1e-10f));
        }
    }
    g_perk[((long)b * WN + w) * NKN + k] = ssum;
}

// ---------------- score + topk(3) with suppression + neighbor gather --------
__global__ void __launch_bounds__(1024) k_final(
    const float* __restrict__ dw, const float* __restrict__ cs,
    float* __restrict__ out)
{
    int b = blockIdx.x;
    int t = threadIdx.x;
    __shared__ float sc[WN], wk[WN];
    __shared__ float rv[1024];
    __shared__ int   ri[1024];
    __shared__ int   tops[3];
    if (t < WN) {
        const float* pk = g_perk + ((long)b * WN + t) * NKN;
        float s = 0.f;
#pragma unroll
        for (int k = 0; k < NKN; k++) s += pk[k] * dw[k];
        if (s == 0.f) s = -9000.f;
        sc[t] = s; wk[t] = s;
    }
    __syncthreads();
    for (int c = 0; c < 3; c++) {
        rv[t] = (t < WN) ? wk[t] : -1e30f;
        ri[t] = t;
        __syncthreads();
        for (int st = 512; st > 0; st >>= 1) {
            if (t < st) {
                float v2 = rv[t + st]; int i2 = ri[t + st];
                if (v2 > rv[t] || (v2 == rv[t] && i2 < ri[t])) { rv[t] = v2; ri[t] = i2; }
            }
            __syncthreads();
        }
        int best = ri[0];
        if (t == 0) tops[c] = best;
        if (t < WN) {
            int d = t - best; if (d < 0) d = -d;
            if (d < SLIDEH) wk[t] = -10001.f - (float)c;
        }
        __syncthreads();
    }
    if (t == 0) {
        const int offs[5] = {0, -1, 1, -2, 2};
        float acc = 0.f;
        for (int g = 0; g < 5; g++)
            for (int c = 0; c < 3; c++) {
                int n = tops[c] + offs[g];
                n = n < 0 ? 0 : (n > WN - 1 ? WN - 1 : n);
                float v = sc[n];
                if (v <= -9000.f) v = 0.f;
                acc += v * cs[g * 3 + c];
            }
        out[b] = acc;
    }
}

// ---------------- host orchestration ----------------------------------------
static void launch_fp8(const uint8_t* A, const uint8_t* B,
                       const float* bias, __nv_bfloat16* C16, uint8_t* C8,
                       int M, int N, int K, int relu, int splits, long zoff) {
    int nx = (N + 127) / 128, ny = (M + 127) / 128, nz = splits;
    int ntile = nx * ny * nz;
    int G = ntile < GPERS ? ntile : GPERS;
    k_gemm_fp8<<<G, 256>>>(A, B, bias, C16, C8, M, N, K, relu, zoff, nx, ny, nz);
}

extern "C" void kernel_launch(void* const* d_in, const int* in_sizes, int n_in,
                              void* d_out, int out_size) {
    (void)in_sizes; (void)n_in; (void)out_size;
    const float* qe   = (const float*)d_in[0];
    const float* de   = (const float*)d_in[1];
    const float* qm   = (const float*)d_in[2];
    const float* dm   = (const float*)d_in[3];
    const float* pq   = (const float*)d_in[4];
    const float* pd   = (const float*)d_in[5];
    const float* Wqkv = (const float*)d_in[6];
    const float* bqkv = (const float*)d_in[7];
    const float* Wo   = (const float*)d_in[8];
    const float* bo   = (const float*)d_in[9];
    const float* ln1g = (const float*)d_in[10];
    const float* ln1b = (const float*)d_in[11];
    const float* Wff1 = (const float*)d_in[12];
    const float* bff1 = (const float*)d_in[13];
    const float* Wff2 = (const float*)d_in[14];
    const float* bff2 = (const float*)d_in[15];
    const float* ln2g = (const float*)d_in[16];
    const float* ln2b = (const float*)d_in[17];
    const float* mixer= (const float*)d_in[18];
    const float* dwp  = (const float*)d_in[19];
    const float* csp  = (const float*)d_in[20];
    const float* mup  = (const float*)d_in[21];
    const float* sgp  = (const float*)d_in[22];
    float* out = (float*)d_out;

    __nv_bfloat16 *p_xb, *p_x1b, *p_qkvh, *p_projh;
    uint8_t *p_xh, *p_x1h, *p_atth, *p_ffh;
    uint8_t *p_wqkvh, *p_woh, *p_wff1h, *p_wff2h;
    cudaGetSymbolAddress((void**)&p_xb,   g_xb);
    cudaGetSymbolAddress((void**)&p_x1b,  g_x1b);
    cudaGetSymbolAddress((void**)&p_qkvh, g_qkvh);
    cudaGetSymbolAddress((void**)&p_projh,g_projh);
    cudaGetSymbolAddress((void**)&p_xh,   g_xh);
    cudaGetSymbolAddress((void**)&p_x1h,  g_x1h);
    cudaGetSymbolAddress((void**)&p_atth, g_atth);
    cudaGetSymbolAddress((void**)&p_ffh,  g_ffh);
    cudaGetSymbolAddress((void**)&p_wqkvh, g_wqkvh);
    cudaGetSymbolAddress((void**)&p_woh,   g_woh);
    cudaGetSymbolAddress((void**)&p_wff1h, g_wff1h);
    cudaGetSymbolAddress((void**)&p_wff2h, g_wff2h);

    const long ZOFF = (long)NTOK * EDIM;
    __nv_bfloat16* p_projh2 = p_projh + ZOFF;

    // launch order: #4 is the first fp8 GEMM (ncu profiles launch #4)
    k_setup<<<(NTOK * EDIM + 255) / 256, 256>>>(qe, de, qm, dm, pq, pd);        // 1
    k_tofp8_all<<<6144, 256>>>(Wqkv, p_wqkvh, Wo, p_woh, Wff1, p_wff1h, Wff2, p_wff2h); // 2
    k_valid<<<(NB * DLEN + 255) / 256, 256>>>(dm);                              // 3

    const uint8_t* xin = p_xh;
    for (int l = 0; l < 2; l++) {
        launch_fp8(xin, p_wqkvh + (long)l * 3 * EDIM * EDIM, bqkv + l * 3 * EDIM,
                   p_qkvh, nullptr, NTOK, 3 * EDIM, EDIM, 0, 1, 0);             // 4 (l=0)
        k_attn<<<NSEQ * HN, 128>>>();
        launch_fp8(p_atth, p_woh + (long)l * EDIM * EDIM, bo + l * EDIM,
                   p_projh, nullptr, NTOK, EDIM, EDIM, 0, 2, ZOFF);
        k_addln<<<NTOK, 128>>>(p_xb, p_projh, p_projh2,
                               ln1g + l * EDIM, ln1b + l * EDIM, p_x1b, p_x1h,
                               mixer, 0);
        launch_fp8(p_x1h, p_wff1h + (long)l * FFD * EDIM, bff1 + l * FFD,
                   nullptr, p_ffh, NTOK, FFD, EDIM, 1, 1, 0);
        launch_fp8(p_ffh, p_wff2h + (long)l * EDIM * FFD, bff2 + l * EDIM,
                   p_projh, nullptr, NTOK, EDIM, FFD, 0, 2, ZOFF);
        k_addln<<<NTOK, 128>>>(p_x1b, p_projh, p_projh2,
                               ln2g + l * EDIM, ln2b + l * EDIM, p_xb, p_xh,
                               mixer, l == 1 ? 1 : 0);
        xin = p_xh;
    }

    {
        dim3 grid((DLEN + 255) / 256, 1, NB);
        k_cos_acts<<<grid, 128>>>(mup, sgp);
    }

    k_wvalid<<<(NB * WN + 255) / 256, 256>>>();
    {
        dim3 grid((WN + 127) / 128, NKN, NB);
        k_perk<<<grid, 128>>>(qm);
    }
    k_final <<<NB, 1024>>>(dwp, csp, out);
}

// round 14
// speedup vs baseline: 1.0596x; 1.0596x over previous
#include <cuda_runtime.h>
#include <cuda_bf16.h>
#include <cuda_fp8.h>
#include <math.h>
#include <stdint.h>

// ---------------- problem constants (fixed shapes from setup_inputs) -------
#define EDIM   512
#define HN     8
#define HD     64
#define FFD    2048
#define NB     8      // batch
#define QLEN   30
#define DLEN   2000
#define CHUNK_ 40
#define OVL    5
#define EXTL   50
#define CPD    50     // chunks per doc
#define NCH    400    // NB*CPD chunk sequences
#define SCH    50     // chunk seq len
#define QBASE  20000  // NCH*SCH
#define NTOK   20240  // QBASE + NB*QLEN
#define NSEQ   408
#define WN     986
#define NKN    11
#define SLIDEH 15

#define FSTR   80     // smem row stride in BYTES (fp8)
#define WSCL     64.0f
#define WSCL_INV 0.015625f
#define PERK_POS 284  // positions staged per perk block (2*127+30)

// ---------------- scratch (device globals; no allocation at runtime) -------
__device__ float g_seq [NTOK*EDIM];
__device__ float g_tmask[NTOK];
__device__ float g_qn  [NB*QLEN*EDIM];
__device__ float g_dn  [NB*DLEN*EDIM];
__device__ float g_valid[NB*DLEN];
__device__ float g_wvalid[NB*WN];
__device__ float g_perk[NB*WN*NKN];
// bf16 intermediates
__device__ __nv_bfloat16 g_xb  [NTOK*EDIM];      // residual stream
__device__ __nv_bfloat16 g_x1b [NTOK*EDIM];      // residual stream (mid)
__device__ __nv_bfloat16 g_qkvh[NTOK*3*EDIM];
__device__ __nv_bfloat16 g_projh[2L*NTOK*EDIM];  // split-K partials
__device__ __nv_bfloat16 g_acts[(long)NB*QLEN*NKN*DLEN];
// fp8 activation / weight copies (e4m3 raw bytes)
__device__ uint8_t g_xh  [NTOK*EDIM];
__device__ uint8_t g_x1h [NTOK*EDIM];
__device__ uint8_t g_atth[NTOK*EDIM];
__device__ uint8_t g_ffh [NTOK*FFD];
__device__ uint8_t g_wqkvh[2*3*EDIM*EDIM];
__device__ uint8_t g_woh  [2*EDIM*EDIM];
__device__ uint8_t g_wff1h[2*FFD*EDIM];
__device__ uint8_t g_wff2h[2*EDIM*FFD];

// ---------------- helpers ---------------------------------------------------
__device__ __forceinline__ float blockSum128(float v) {
    __shared__ float sh[4];
#pragma unroll
    for (int o = 16; o > 0; o >>= 1) v += __shfl_xor_sync(0xffffffffu, v, o);
    if ((threadIdx.x & 31) == 0) sh[threadIdx.x >> 5] = v;
    __syncthreads();
    float t = sh[0] + sh[1] + sh[2] + sh[3];
    __syncthreads();
    return t;
}
__device__ __forceinline__ uint8_t f2fp8(float x) {
    return (uint8_t)__nv_cvt_float_to_fp8(x, __NV_SATFINITE, __NV_E4M3);
}
__device__ __forceinline__ uint16_t pack2fp8(float lo, float hi) {
    uint16_t r;
    asm("cvt.rn.satfinite.e4m3x2.f32 %0, %1, %2;" : "=h"(r) : "f"(hi), "f"(lo));
    return r;
}
__device__ __forceinline__ void cpasync16s(uint32_t saddr, const void* gmem, bool pred) {
    int sz = pred ? 16 : 0;
    asm volatile("cp.async.cg.shared.global [%0], [%1], 16, %2;\n"
                 :: "r"(saddr), "l"(gmem), "r"(sz));
}
__device__ __forceinline__ void mma_fp8(float* d, const uint32_t* a, const uint32_t* b) {
    asm volatile(
        "mma.sync.aligned.m16n8k32.row.col.f32.e4m3.e4m3.f32 "
        "{%0,%1,%2,%3}, {%4,%5,%6,%7}, {%8,%9}, {%0,%1,%2,%3};\n"
        : "+f"(d[0]), "+f"(d[1]), "+f"(d[2]), "+f"(d[3])
        : "r"(a[0]), "r"(a[1]), "r"(a[2]), "r"(a[3]), "r"(b[0]), "r"(b[1]));
}
__device__ __forceinline__ void ldmx4(uint32_t* r, uint32_t saddr) {
    asm volatile("ldmatrix.sync.aligned.m8n8.x4.shared.b16 {%0,%1,%2,%3}, [%4];"
                 : "=r"(r[0]), "=r"(r[1]), "=r"(r[2]), "=r"(r[3]) : "r"(saddr));
}

// ---------------- fp32 -> fp8 conversion, all 4 weight tensors in one launch
__global__ void k_tofp8_all(const float* __restrict__ s0, uint8_t* __restrict__ d0,
                            const float* __restrict__ s1, uint8_t* __restrict__ d1,
                            const float* __restrict__ s2, uint8_t* __restrict__ d2,
                            const float* __restrict__ s3, uint8_t* __restrict__ d3) {
    int blk = blockIdx.x;
    const float* src; uint8_t* dst; long base;
    if (blk < 1536)      { src = s0; dst = d0; base = (long)blk * 1024; }
    else if (blk < 2048) { src = s1; dst = d1; base = (long)(blk - 1536) * 1024; }
    else if (blk < 4096) { src = s2; dst = d2; base = (long)(blk - 2048) * 1024; }
    else                 { src = s3; dst = d3; base = (long)(blk - 4096) * 1024; }
    long i = base + (long)threadIdx.x * 4;
    float4 v = *(const float4*)(src + i);
    uint32_t pk = (uint32_t)pack2fp8(v.x * WSCL, v.y * WSCL)
                | ((uint32_t)pack2fp8(v.z * WSCL, v.w * WSCL) << 16);
    *(uint32_t*)(dst + i) = pk;
}

// ---------------- setup: gather chunked docs + queries, add pos ------------
__global__ void k_setup(const float* __restrict__ qe, const float* __restrict__ de,
                        const float* __restrict__ qm, const float* __restrict__ dm,
                        const float* __restrict__ pq, const float* __restrict__ pd) {
    long gid = (long)blockIdx.x * 256 + threadIdx.x;
    if (gid >= (long)NTOK * EDIM) return;
    int tok = (int)(gid >> 9);
    int e = (int)(gid & 511);
    float val, pos, mk;
    if (tok < QBASE) {
        int s = tok / SCH, t = tok % SCH;
        int b = s / CPD, c = s % CPD;
        int j = c * CHUNK_ + t - OVL;
        if (j >= 0 && j < DLEN) {
            val = de[((long)(b * DLEN + j)) * EDIM + e];
            mk  = dm[b * DLEN + j];
        } else { val = 0.f; mk = 0.f; }
        pos = pd[t * EDIM + e];
    } else {
        int i2 = tok - QBASE; int b = i2 / QLEN, t = i2 % QLEN;
        val = qe[((long)(b * QLEN + t)) * EDIM + e];
        mk  = qm[b * QLEN + t];
        pos = pq[t * EDIM + e];
    }
    g_seq[gid] = val;
    float xv = val + pos;
    g_xb[gid] = __float2bfloat16(xv);
    g_xh[gid] = f2fp8(xv);
    if (e == 0) g_tmask[tok] = mk;
}

// ---------------- fp8 tensor-core GEMM: C[M,N] = A[M,K]@B[N,K]^T -----------
// 128x128 tile, BK=64, 256 threads (8 warps 2x4), warp tile 64x32,
// m16n8k32 e4m3 mma, ldmatrix.x4 loads, double-buffered cp.async,
// register-held global pointers. split-K via gridDim.z. (non-persistent)
__global__ void __launch_bounds__(256, 2) k_gemm_fp8(
    const uint8_t* __restrict__ A, const uint8_t* __restrict__ B,
    const float* __restrict__ Bias, __nv_bfloat16* __restrict__ C16,
    uint8_t* __restrict__ C8, int M, int N, int K, int relu, long zoff)
{
    __shared__ uint8_t As[2][128 * FSTR];
    __shared__ uint8_t Bs[2][128 * FSTR];
    int m0 = blockIdx.y * 128, n0 = blockIdx.x * 128;
    int splits = gridDim.z;
    int Keff = K / splits;
    int kbeg = blockIdx.z * Keff;
    const float* Biasz = (blockIdx.z == 0) ? Bias : nullptr;
    __nv_bfloat16* C16z = C16 ? (C16 + (blockIdx.z ? zoff : 0)) : nullptr;

    int tid = threadIdx.x;
    int warp = tid >> 5, lane = tid & 31;
    int wm = (warp >> 2) * 64, wn = (warp & 3) * 32;
    int gid = lane >> 2, tig = lane & 3;

    float acc[4][4][4];
#pragma unroll
    for (int i = 0; i < 4; i++)
#pragma unroll
        for (int j = 0; j < 4; j++)
#pragma unroll
            for (int r = 0; r < 4; r++) acc[i][j][r] = 0.f;

    int row = tid >> 2;
    int q   = tid & 3;

    bool pm[2], pn[2];
    const uint8_t* aP[2];
    const uint8_t* bP[2];
    uint32_t sA[2][2], sB[2][2];   // [buf][i]
#pragma unroll
    for (int i = 0; i < 2; i++) {
        int r = row + i * 64;
        int gm = m0 + r; pm[i] = gm < M; int gmr = pm[i] ? gm : (M - 1);
        int gn = n0 + r; pn[i] = gn < N; int gnr = pn[i] ? gn : (N - 1);
        aP[i] = A + (long)gmr * K + kbeg + q * 16;
        bP[i] = B + (long)gnr * K + kbeg + q * 16;
#pragma unroll
        for (int b = 0; b < 2; b++) {
            sA[b][i] = (uint32_t)__cvta_generic_to_shared(&As[b][r * FSTR + q * 16]);
            sB[b][i] = (uint32_t)__cvta_generic_to_shared(&Bs[b][r * FSTR + q * 16]);
        }
    }

    int l8 = lane & 7;
    uint32_t aBase[2], bBase[2];
    {
        int aRow = wm + l8 + ((lane & 8) ? 8 : 0);
        uint32_t aOff = (uint32_t)(aRow * FSTR) + ((lane & 16) ? 16u : 0u);
        int bRow = wn + l8 + ((lane & 16) ? 8 : 0);
        uint32_t bOff = (uint32_t)(bRow * FSTR) + ((lane & 8) ? 16u : 0u);
#pragma unroll
        for (int b = 0; b < 2; b++) {
            aBase[b] = (uint32_t)__cvta_generic_to_shared(&As[b][0]) + aOff;
            bBase[b] = (uint32_t)__cvta_generic_to_shared(&Bs[b][0]) + bOff;
        }
    }

    int nk = Keff >> 6;
    {   // prologue: tile 0 -> buf 0
#pragma unroll
        for (int i = 0; i < 2; i++) {
            cpasync16s(sA[0][i], aP[i], pm[i]);
            cpasync16s(sB[0][i], bP[i], pn[i]);
            aP[i] += 64; bP[i] += 64;
        }
        asm volatile("cp.async.commit_group;\n");
    }

    int buf = 0;
    for (int kt = 0; kt < nk; kt++) {
        asm volatile("cp.async.wait_group 0;\n");
        __syncthreads();
        if (kt + 1 < nk) {
            int nb = buf ^ 1;
#pragma unroll
            for (int i = 0; i < 2; i++) {
                cpasync16s(sA[nb][i], aP[i], pm[i]);
                cpasync16s(sB[nb][i], bP[i], pn[i]);
                aP[i] += 64; bP[i] += 64;
            }
            asm volatile("cp.async.commit_group;\n");
        }
#pragma unroll
        for (int ks = 0; ks < 2; ks++) {
            uint32_t koff = (uint32_t)(ks * 32);
            uint32_t af[4][4], bfr[2][4];
#pragma unroll
            for (int mi = 0; mi < 4; mi++)
                ldmx4(af[mi], aBase[buf] + koff + (uint32_t)(mi * 16 * FSTR));
            ldmx4(bfr[0], bBase[buf] + koff);
            ldmx4(bfr[1], bBase[buf] + koff + (uint32_t)(16 * FSTR));
#pragma unroll
            for (int mi = 0; mi < 4; mi++)
#pragma unroll
                for (int ni = 0; ni < 4; ni++)
                    mma_fp8(acc[mi][ni], af[mi], &bfr[ni >> 1][(ni & 1) * 2]);
        }
        buf ^= 1;
        __syncthreads();
    }

#pragma unroll
    for (int mi = 0; mi < 4; mi++) {
        int r0 = m0 + wm + mi * 16 + gid;
        int r1 = r0 + 8;
#pragma unroll
        for (int ni = 0; ni < 4; ni++) {
            int cb = n0 + wn + ni * 8 + 2 * tig;
            float b0 = Biasz ? Biasz[cb] : 0.f;
            float b1 = Biasz ? Biasz[cb + 1] : 0.f;
            float v0 = acc[mi][ni][0] * WSCL_INV + b0, v1 = acc[mi][ni][1] * WSCL_INV + b1;
            float v2 = acc[mi][ni][2] * WSCL_INV + b0, v3 = acc[mi][ni][3] * WSCL_INV + b1;
            if (relu) { v0 = fmaxf(v0, 0.f); v1 = fmaxf(v1, 0.f);
                        v2 = fmaxf(v2, 0.f); v3 = fmaxf(v3, 0.f); }
            if (C16z) {
                if (r0 < M) *(__nv_bfloat162*)(C16z + (long)r0 * N + cb) = __floats2bfloat162_rn(v0, v1);
                if (r1 < M) *(__nv_bfloat162*)(C16z + (long)r1 * N + cb) = __floats2bfloat162_rn(v2, v3);
            }
            if (C8) {
                if (r0 < M) *(uint16_t*)(C8 + (long)r0 * N + cb) = pack2fp8(v0, v1);
                if (r1 < M) *(uint16_t*)(C8 + (long)r1 * N + cb) = pack2fp8(v2, v3);
            }
        }
    }
}

// ---------------- fused cos GEMM + RBF acts ----------------------------------
// cos[b,q,d] = qn[b,q,:]·dn[b,d,:]; acts written directly as packed bf16.
__global__ void __launch_bounds__(128) k_cos_acts(
    const float* __restrict__ mup, const float* __restrict__ sgp)
{
    __shared__ float As[16][32];
    __shared__ float Bs[16][260];
    __shared__ float mu[NKN], i2s[NKN];
    int b = blockIdx.z;
    int n0 = blockIdx.x * 256;
    const float* A = g_qn + (long)b * QLEN * EDIM;
    const float* B = g_dn + (long)b * DLEN * EDIM;
    int tid = threadIdx.x;
    if (tid < NKN) {
        mu[tid] = mup[tid];
        float sg = sgp[tid];
        i2s[tid] = 1.f / (2.f * sg * sg);
    }
    int ty = tid >> 5, tx = tid & 31;
    float acc[8][8];
#pragma unroll
    for (int i = 0; i < 8; i++)
#pragma unroll
        for (int j = 0; j < 8; j++) acc[i][j] = 0.f;

    for (int k0 = 0; k0 < EDIM; k0 += 16) {
        {
            int r = tid >> 2, c = (tid & 3) << 2;
            float4 v = make_float4(0.f, 0.f, 0.f, 0.f);
            if (r < QLEN) v = *(const float4*)(A + (long)r * EDIM + k0 + c);
            As[c + 0][r] = v.x; As[c + 1][r] = v.y; As[c + 2][r] = v.z; As[c + 3][r] = v.w;
        }
#pragma unroll
        for (int j = 0; j < 8; j++) {
            int idx = tid + 128 * j;
            int r = idx >> 2, c = (idx & 3) << 2;
            int gn = n0 + r;
            float4 v = make_float4(0.f, 0.f, 0.f, 0.f);
            if (gn < DLEN) v = *(const float4*)(B + (long)gn * EDIM + k0 + c);
            Bs[c + 0][r] = v.x; Bs[c + 1][r] = v.y; Bs[c + 2][r] = v.z; Bs[c + 3][r] = v.w;
        }
        __syncthreads();
#pragma unroll
        for (int kk = 0; kk < 16; kk++) {
            float a[8], bb[8];
            *(float4*)(a)      = *(const float4*)(&As[kk][ty * 8]);
            *(float4*)(a + 4)  = *(const float4*)(&As[kk][ty * 8 + 4]);
            *(float4*)(bb)     = *(const float4*)(&Bs[kk][tx * 8]);
            *(float4*)(bb + 4) = *(const float4*)(&Bs[kk][tx * 8 + 4]);
#pragma unroll
            for (int i = 0; i < 8; i++)
#pragma unroll
                for (int j = 0; j < 8; j++) acc[i][j] = fmaf(a[i], bb[j], acc[i][j]);
        }
        __syncthreads();
    }
    // epilogue: RBF kernels + mask, packed bf16 stores (16B per (row,k))
    int p8 = n0 + tx * 8;
    float vd[8];
#pragma unroll
    for (int j = 0; j < 8; j++) {
        int p = p8 + j;
        vd[j] = (p < DLEN) ? g_valid[b * DLEN + p] : 0.f;
    }
    bool full = (p8 + 8 <= DLEN);
#pragma unroll
    for (int i = 0; i < 8; i++) {
        int m = ty * 8 + i;
        if (m >= QLEN) continue;
        long rowbase = ((long)(b * QLEN + m)) * NKN;
#pragma unroll
        for (int k = 0; k < NKN; k++) {
            __align__(16) __nv_bfloat16 tmp[8];
#pragma unroll
            for (int j = 0; j < 8; j++) {
                float d = acc[i][j] - mu[k];
                tmp[j] = __float2bfloat16(__expf(-d * d * i2s[k]) * vd[j]);
            }
            __nv_bfloat16* addr = g_acts + (rowbase + k) * DLEN + p8;
            if (full) *(uint4*)addr = *(uint4*)tmp;
            else {
                for (int j = 0; j < 8 && p8 + j < DLEN; j++) addr[j] = tmp[j];
            }
        }
    }
}

// ---------------- attention: one block per (sequence, head), 2-row unroll --
__global__ void __launch_bounds__(128) k_attn() {
    int bid = blockIdx.x;
    int s = bid >> 3, h = bid & 7;
    int S, base;
    if (s < NCH) { S = SCH; base = s * SCH; }
    else         { S = QLEN; base = QBASE + (s - NCH) * QLEN; }
    __shared__ float Qs[SCH * HD];
    __shared__ float Kt[HD * 52];
    __shared__ float Vs[SCH * HD];
    __shared__ float mk[52];
    __shared__ float Pw[4][2][52];
    int tid = threadIdx.x;
    for (int idx = tid; idx < S * HD; idx += 128) {
        int r = idx >> 6, d = idx & 63;
        const __nv_bfloat16* row = g_qkvh + (long)(base + r) * (3 * EDIM) + h * HD;
        Qs[idx]        = __bfloat162float(row[d]);
        Kt[d * 52 + r] = __bfloat162float(row[EDIM + d]);
        Vs[idx]        = __bfloat162float(row[2 * EDIM + d]);
    }
    if (tid < S) mk[tid] = g_tmask[base + tid];
    __syncthreads();
    int warp = tid >> 5, lane = tid & 31;
    int j0 = lane, j1 = lane + 32;
    bool v0ok = j0 < S, v1ok;
    for (int i = warp; i < S; i += 8) {
        int ib = i + 4;
        bool has2 = ib < S;
        int ibc = has2 ? ib : i;
        float s0a = -1e30f, s1a = -1e30f, s0b = -1e30f, s1b = -1e30f;
        v1ok = j1 < S;
        if (v0ok) {
            float aa = 0.f, ab = 0.f;
#pragma unroll
            for (int d = 0; d < HD; d++) {
                float kv = Kt[d * 52 + j0];
                aa = fmaf(Qs[i * HD + d], kv, aa);
                ab = fmaf(Qs[ibc * HD + d], kv, ab);
            }
            s0a = (mk[j0] > 0.f) ? aa * 0.125f : -1e9f;
            s0b = (mk[j0] > 0.f) ? ab * 0.125f : -1e9f;
        }
        if (v1ok) {
            float aa = 0.f, ab = 0.f;
#pragma unroll
            for (int d = 0; d < HD; d++) {
                float kv = Kt[d * 52 + j1];
                aa = fmaf(Qs[i * HD + d], kv, aa);
                ab = fmaf(Qs[ibc * HD + d], kv, ab);
            }
            s1a = (mk[j1] > 0.f) ? aa * 0.125f : -1e9f;
            s1b = (mk[j1] > 0.f) ? ab * 0.125f : -1e9f;
        }
        float ma = fmaxf(s0a, s1a);
#pragma unroll
        for (int o = 16; o > 0; o >>= 1) ma = fmaxf(ma, __shfl_xor_sync(0xffffffffu, ma, o));
        float e0a = v0ok ? __expf(s0a - ma) : 0.f;
        float e1a = v1ok ? __expf(s1a - ma) : 0.f;
        float za = e0a + e1a;
#pragma unroll
        for (int o = 16; o > 0; o >>= 1) za += __shfl_xor_sync(0xffffffffu, za, o);
        float inva = 1.f / za;
        if (v0ok) Pw[warp][0][j0] = e0a * inva;
        if (v1ok) Pw[warp][0][j1] = e1a * inva;
        float mb = fmaxf(s0b, s1b);
#pragma unroll
        for (int o = 16; o > 0; o >>= 1) mb = fmaxf(mb, __shfl_xor_sync(0xffffffffu, mb, o));
        float e0b = v0ok ? __expf(s0b - mb) : 0.f;
        float e1b = v1ok ? __expf(s1b - mb) : 0.f;
        float zb = e0b + e1b;
#pragma unroll
        for (int o = 16; o > 0; o >>= 1) zb += __shfl_xor_sync(0xffffffffu, zb, o);
        float invb = 1.f / zb;
        if (v0ok) Pw[warp][1][j0] = e0b * invb;
        if (v1ok) Pw[warp][1][j1] = e1b * invb;
        __syncwarp();
        float o0a = 0.f, o1a = 0.f, o0b = 0.f, o1b = 0.f;
        for (int j = 0; j < S; j++) {
            float pa = Pw[warp][0][j];
            float pb = Pw[warp][1][j];
            float v0 = Vs[j * HD + lane];
            float v1 = Vs[j * HD + lane + 32];
            o0a = fmaf(pa, v0, o0a); o1a = fmaf(pa, v1, o1a);
            o0b = fmaf(pb, v0, o0b); o1b = fmaf(pb, v1, o1b);
        }
        long orow = (long)(base + i) * EDIM + h * HD;
        g_atth[orow + lane]      = f2fp8(o0a);
        g_atth[orow + lane + 32] = f2fp8(o1a);
        if (has2) {
            long orow2 = (long)(base + ib) * EDIM + h * HD;
            g_atth[orow2 + lane]      = f2fp8(o0b);
            g_atth[orow2 + lane + 32] = f2fp8(o1b);
        }
        __syncwarp();
    }
}

// ---------------- residual-add + layernorm ----------------------------------
// finalflag=0: store bf16 + fp8 copies. finalflag=1 (last LN): fuse repnorm.
__global__ void __launch_bounds__(128) k_addln(
    const __nv_bfloat16* __restrict__ X, const __nv_bfloat16* __restrict__ Y,
    const __nv_bfloat16* __restrict__ Y2,
    const float* __restrict__ G, const float* __restrict__ Bv,
    __nv_bfloat16* __restrict__ Out, uint8_t* __restrict__ OutH,
    const float* __restrict__ mixer, int finalflag)
{
    long tok = blockIdx.x;
    int t = threadIdx.x;
    float* dst = nullptr;
    if (finalflag) {
        int tokc = (int)tok;
        if (tokc < QBASE) {
            int s = tokc / SCH, tt = tokc % SCH;
            int tl = tt - OVL;
            if (tl < 0 || tl >= CHUNK_) return;
            int b = s / CPD, c = s % CPD;
            dst = g_dn + ((long)(b * DLEN + c * CHUNK_ + tl)) * EDIM;
        } else {
            dst = g_qn + (long)(tokc - QBASE) * EDIM;
        }
    }
    __nv_bfloat162 x0 = *(const __nv_bfloat162*)(X + tok * EDIM + t * 4);
    __nv_bfloat162 x1 = *(const __nv_bfloat162*)(X + tok * EDIM + t * 4 + 2);
    __nv_bfloat162 y0 = *(const __nv_bfloat162*)(Y + tok * EDIM + t * 4);
    __nv_bfloat162 y1 = *(const __nv_bfloat162*)(Y + tok * EDIM + t * 4 + 2);
    __nv_bfloat162 z0 = *(const __nv_bfloat162*)(Y2 + tok * EDIM + t * 4);
    __nv_bfloat162 z1 = *(const __nv_bfloat162*)(Y2 + tok * EDIM + t * 4 + 2);
    float4 v = make_float4(
        __bfloat162float(x0.x) + __bfloat162float(y0.x) + __bfloat162float(z0.x),
        __bfloat162float(x0.y) + __bfloat162float(y0.y) + __bfloat162float(z0.y),
        __bfloat162float(x1.x) + __bfloat162float(y1.x) + __bfloat162float(z1.x),
        __bfloat162float(x1.y) + __bfloat162float(y1.y) + __bfloat162float(z1.y));
    float s = blockSum128(v.x + v.y + v.z + v.w);
    float mean = s * (1.f / 512.f);
    float dx = v.x - mean, dy = v.y - mean, dz = v.z - mean, dw = v.w - mean;
    float sq = blockSum128(dx * dx + dy * dy + dz * dz + dw * dw);
    float rstd = rsqrtf(sq * (1.f / 512.f) + 1e-5f);
    float4 g = ((const float4*)G)[t], bb = ((const float4*)Bv)[t];
    float4 o = make_float4(dx * rstd * g.x + bb.x, dy * rstd * g.y + bb.y,
                           dz * rstd * g.z + bb.z, dw * rstd * g.w + bb.w);
    if (!finalflag) {
        *(__nv_bfloat162*)(Out + tok * EDIM + t * 4)     = __floats2bfloat162_rn(o.x, o.y);
        *(__nv_bfloat162*)(Out + tok * EDIM + t * 4 + 2) = __floats2bfloat162_rn(o.z, o.w);
        uint32_t pk = (uint32_t)pack2fp8(o.x, o.y) | ((uint32_t)pack2fp8(o.z, o.w) << 16);
        *(uint32_t*)(OutH + tok * EDIM + t * 4) = pk;
        return;
    }
    float mx = mixer[0];
    float mkv = g_tmask[tok];
    float4 sv = ((const float4*)(g_seq + tok * EDIM))[t];
    float4 r = make_float4((mx * sv.x + (1.f - mx) * o.x) * mkv,
                           (mx * sv.y + (1.f - mx) * o.y) * mkv,
                           (mx * sv.z + (1.f - mx) * o.z) * mkv,
                           (mx * sv.w + (1.f - mx) * o.w) * mkv);
    float sq2 = blockSum128(r.x * r.x + r.y * r.y + r.z * r.z + r.w * r.w);
    float inv = 1.f / (sqrtf(sq2) + 1e-13f);
    ((float4*)dst)[t] = make_float4(r.x * inv, r.y * inv, r.z * inv, r.w * inv);
}

// ---------------- per-position validity (m_in * packed) --------------------
__global__ void k_valid(const float* __restrict__ dm) {
    int gid = blockIdx.x * 256 + threadIdx.x;
    if (gid >= NB * DLEN) return;
    int b = gid / DLEN, p = gid % DLEN;
    int c = p / CHUNK_;
    float s = 0.f;
    for (int d = 0; d < CHUNK_; d++) s += dm[b * DLEN + c * CHUNK_ + d];
    float packed = (s != 0.f) ? 1.f : 0.f;
    g_valid[gid] = dm[b * DLEN + p] * packed;
}

// ---------------- window validity -------------------------------------------
__global__ void k_wvalid() {
    int gid = blockIdx.x * 256 + threadIdx.x;
    if (gid >= NB * WN) return;
    int b = gid / WN, w = gid % WN;
    float any = 0.f;
    for (int i = 0; i < 30; i++)
        if (g_valid[b * DLEN + 2 * w + i] != 0.f) any = 1.f;
    g_wvalid[gid] = any;
}

// ---------------- per-kernel window log-saturation (smem-staged, bf16 src) --
__global__ void __launch_bounds__(128) k_perk(const float* __restrict__ qm) {
    __shared__ float sa[QLEN][PERK_POS];
    __shared__ float qms[QLEN];
    int wt = blockIdx.x, k = blockIdx.y, b = blockIdx.z;
    int w0 = wt * 128;
    int p0 = 2 * w0;
    int npos = DLEN - p0; if (npos > PERK_POS) npos = PERK_POS;
    int tid = threadIdx.x;
    for (int idx = tid; idx < QLEN * npos; idx += 128) {
        int q = idx / npos, j = idx % npos;
        sa[q][j] = __bfloat162float(
            g_acts[(((long)(b * QLEN + q)) * NKN + k) * DLEN + p0 + j]);
    }
    if (tid < QLEN) qms[tid] = qm[b * QLEN + tid];
    __syncthreads();
    int w = w0 + tid;
    if (w >= WN) return;
    float wv = g_wvalid[b * WN + w];
    float ssum = 0.f;
    if (wv != 0.f) {
        int off = 2 * tid;
        for (int q = 0; q < QLEN; q++) {
            float pkq = 0.f;
#pragma unroll
            for (int i = 0; i < 30; i++) pkq += sa[q][off + i];
            ssum += qms[q] * logf(fmaxf(pkq, 1e-10f));
        }
    }
    g_perk[((long)b * WN + w) * NKN + k] = ssum;
}

// ---------------- score + topk(3) with suppression + neighbor gather --------
__global__ void __launch_bounds__(1024) k_final(
    const float* __restrict__ dw, const float* __restrict__ cs,
    float* __restrict__ out)
{
    int b = blockIdx.x;
    int t = threadIdx.x;
    __shared__ float sc[WN], wk[WN];
    __shared__ float rv[1024];
    __shared__ int   ri[1024];
    __shared__ int   tops[3];
    if (t < WN) {
        const float* pk = g_perk + ((long)b * WN + t) * NKN;
        float s = 0.f;
#pragma unroll
        for (int k = 0; k < NKN; k++) s += pk[k] * dw[k];
        if (s == 0.f) s = -9000.f;
        sc[t] = s; wk[t] = s;
    }
    __syncthreads();
    for (int c = 0; c < 3; c++) {
        rv[t] = (t < WN) ? wk[t] : -1e30f;
        ri[t] = t;
        __syncthreads();
        for (int st = 512; st > 0; st >>= 1) {
            if (t < st) {
                float v2 = rv[t + st]; int i2 = ri[t + st];
                if (v2 > rv[t] || (v2 == rv[t] && i2 < ri[t])) { rv[t] = v2; ri[t] = i2; }
            }
            __syncthreads();
        }
        int best = ri[0];
        if (t == 0) tops[c] = best;
        if (t < WN) {
            int d = t - best; if (d < 0) d = -d;
            if (d < SLIDEH) wk[t] = -10001.f - (float)c;
        }
        __syncthreads();
    }
    if (t == 0) {
        const int offs[5] = {0, -1, 1, -2, 2};
        float acc = 0.f;
        for (int g = 0; g < 5; g++)
            for (int c = 0; c < 3; c++) {
                int n = tops[c] + offs[g];
                n = n < 0 ? 0 : (n > WN - 1 ? WN - 1 : n);
                float v = sc[n];
                if (v <= -9000.f) v = 0.f;
                acc += v * cs[g * 3 + c];
            }
        out[b] = acc;
    }
}

// ---------------- host orchestration ----------------------------------------
static void launch_fp8(const uint8_t* A, const uint8_t* B,
                       const float* bias, __nv_bfloat16* C16, uint8_t* C8,
                       int M, int N, int K, int relu, int splits, long zoff) {
    dim3 grid((N + 127) / 128, (M + 127) / 128, splits);
    k_gemm_fp8<<<grid, 256>>>(A, B, bias, C16, C8, M, N, K, relu, zoff);
}

extern "C" void kernel_launch(void* const* d_in, const int* in_sizes, int n_in,
                              void* d_out, int out_size) {
    (void)in_sizes; (void)n_in; (void)out_size;
    const float* qe   = (const float*)d_in[0];
    const float* de   = (const float*)d_in[1];
    const float* qm   = (const float*)d_in[2];
    const float* dm   = (const float*)d_in[3];
    const float* pq   = (const float*)d_in[4];
    const float* pd   = (const float*)d_in[5];
    const float* Wqkv = (const float*)d_in[6];
    const float* bqkv = (const float*)d_in[7];
    const float* Wo   = (const float*)d_in[8];
    const float* bo   = (const float*)d_in[9];
    const float* ln1g = (const float*)d_in[10];
    const float* ln1b = (const float*)d_in[11];
    const float* Wff1 = (const float*)d_in[12];
    const float* bff1 = (const float*)d_in[13];
    const float* Wff2 = (const float*)d_in[14];
    const float* bff2 = (const float*)d_in[15];
    const float* ln2g = (const float*)d_in[16];
    const float* ln2b = (const float*)d_in[17];
    const float* mixer= (const float*)d_in[18];
    const float* dwp  = (const float*)d_in[19];
    const float* csp  = (const float*)d_in[20];
    const float* mup  = (const float*)d_in[21];
    const float* sgp  = (const float*)d_in[22];
    float* out = (float*)d_out;

    __nv_bfloat16 *p_xb, *p_x1b, *p_qkvh, *p_projh;
    uint8_t *p_xh, *p_x1h, *p_atth, *p_ffh;
    uint8_t *p_wqkvh, *p_woh, *p_wff1h, *p_wff2h;
    cudaGetSymbolAddress((void**)&p_xb,   g_xb);
    cudaGetSymbolAddress((void**)&p_x1b,  g_x1b);
    cudaGetSymbolAddress((void**)&p_qkvh, g_qkvh);
    cudaGetSymbolAddress((void**)&p_projh,g_projh);
    cudaGetSymbolAddress((void**)&p_xh,   g_xh);
    cudaGetSymbolAddress((void**)&p_x1h,  g_x1h);
    cudaGetSymbolAddress((void**)&p_atth, g_atth);
    cudaGetSymbolAddress((void**)&p_ffh,  g_ffh);
    cudaGetSymbolAddress((void**)&p_wqkvh, g_wqkvh);
    cudaGetSymbolAddress((void**)&p_woh,   g_woh);
    cudaGetSymbolAddress((void**)&p_wff1h, g_wff1h);
    cudaGetSymbolAddress((void**)&p_wff2h, g_wff2h);

    const long ZOFF = (long)NTOK * EDIM;
    __nv_bfloat16* p_projh2 = p_projh + ZOFF;

    // launch order: #4 is the first fp8 GEMM (ncu profiles launch #4)
    k_setup<<<(NTOK * EDIM + 255) / 256, 256>>>(qe, de, qm, dm, pq, pd);        // 1
    k_tofp8_all<<<6144, 256>>>(Wqkv, p_wqkvh, Wo, p_woh, Wff1, p_wff1h, Wff2, p_wff2h); // 2
    k_valid<<<(NB * DLEN + 255) / 256, 256>>>(dm);                              // 3

    const uint8_t* xin = p_xh;
    for (int l = 0; l < 2; l++) {
        launch_fp8(xin, p_wqkvh + (long)l * 3 * EDIM * EDIM, bqkv + l * 3 * EDIM,
                   p_qkvh, nullptr, NTOK, 3 * EDIM, EDIM, 0, 1, 0);             // 4 (l=0)
        k_attn<<<NSEQ * HN, 128>>>();
        launch_fp8(p_atth, p_woh + (long)l * EDIM * EDIM, bo + l * EDIM,
                   p_projh, nullptr, NTOK, EDIM, EDIM, 0, 2, ZOFF);
        k_addln<<<NTOK, 128>>>(p_xb, p_projh, p_projh2,
                               ln1g + l * EDIM, ln1b + l * EDIM, p_x1b, p_x1h,
                               mixer, 0);
        launch_fp8(p_x1h, p_wff1h + (long)l * FFD * EDIM, bff1 + l * FFD,
                   nullptr, p_ffh, NTOK, FFD, EDIM, 1, 1, 0);
        launch_fp8(p_ffh, p_wff2h + (long)l * EDIM * FFD, bff2 + l * EDIM,
                   p_projh, nullptr, NTOK, EDIM, FFD, 0, 2, ZOFF);
        k_addln<<<NTOK, 128>>>(p_x1b, p_projh, p_projh2,
                               ln2g + l * EDIM, ln2b + l * EDIM, p_xb, p_xh,
                               mixer, l == 1 ? 1 : 0);
        xin = p_xh;
    }

    {
        dim3 grid((DLEN + 255) / 256, 1, NB);
        k_cos_acts<<<grid, 128>>>(mup, sgp);
    }

    k_wvalid<<<(NB * WN + 255) / 256, 256>>>();
    {
        dim3 grid((WN + 127) / 128, NKN, NB);
        k_perk<<<grid, 128>>>(qm);
    }
    k_final <<<NB, 1024>>>(dwp, csp, out);
}

// round 15
// speedup vs baseline: 1.1116x; 1.0491x over previous
#include <cuda_runtime.h>
#include <cuda_bf16.h>
#include <cuda_fp8.h>
#include <math.h>
#include <stdint.h>

// ---------------- problem constants (fixed shapes from setup_inputs) -------
#define EDIM   512
#define HN     8
#define HD     64
#define FFD    2048
#define NB     8      // batch
#define QLEN   30
#define DLEN   2000
#define CHUNK_ 40
#define OVL    5
#define EXTL   50
#define CPD    50     // chunks per doc
#define NCH    400    // NB*CPD chunk sequences
#define SCH    50     // chunk seq len
#define QBASE  20000  // NCH*SCH
#define NTOK   20240  // QBASE + NB*QLEN
#define NSEQ   408
#define WN     986
#define NKN    11
#define SLIDEH 15

#define FSTR   80     // smem row stride in BYTES (fp8)
#define WSCL     64.0f
#define WSCL_INV 0.015625f
#define PERK_POS 284  // positions staged per perk block (2*127+30)

// ---------------- scratch (device globals; no allocation at runtime) -------
__device__ float g_seq [NTOK*EDIM];
__device__ float g_tmask[NTOK];
__device__ float g_qn  [NB*QLEN*EDIM];
__device__ float g_dn  [NB*DLEN*EDIM];
__device__ float g_cos [NB*QLEN*DLEN];
__device__ float g_valid[NB*DLEN];
__device__ float g_perk[NB*WN*NKN];
// bf16 intermediates
__device__ __nv_bfloat16 g_xb  [NTOK*EDIM];      // residual stream
__device__ __nv_bfloat16 g_x1b [NTOK*EDIM];      // residual stream (mid)
__device__ __nv_bfloat16 g_qkvh[NTOK*3*EDIM];
__device__ __nv_bfloat16 g_projh[2L*NTOK*EDIM];  // split-K partials
__device__ __nv_bfloat16 g_acts[(long)NB*QLEN*NKN*DLEN];
// fp8 activation / weight copies (e4m3 raw bytes)
__device__ uint8_t g_xh  [NTOK*EDIM];
__device__ uint8_t g_x1h [NTOK*EDIM];
__device__ uint8_t g_atth[NTOK*EDIM];
__device__ uint8_t g_ffh [NTOK*FFD];
__device__ uint8_t g_wqkvh[2*3*EDIM*EDIM];
__device__ uint8_t g_woh  [2*EDIM*EDIM];
__device__ uint8_t g_wff1h[2*FFD*EDIM];
__device__ uint8_t g_wff2h[2*EDIM*FFD];

// ---------------- helpers ---------------------------------------------------
__device__ __forceinline__ float blockSum128(float v) {
    __shared__ float sh[4];
#pragma unroll
    for (int o = 16; o > 0; o >>= 1) v += __shfl_xor_sync(0xffffffffu, v, o);
    if ((threadIdx.x & 31) == 0) sh[threadIdx.x >> 5] = v;
    __syncthreads();
    float t = sh[0] + sh[1] + sh[2] + sh[3];
    __syncthreads();
    return t;
}
__device__ __forceinline__ uint8_t f2fp8(float x) {
    return (uint8_t)__nv_cvt_float_to_fp8(x, __NV_SATFINITE, __NV_E4M3);
}
__device__ __forceinline__ uint16_t pack2fp8(float lo, float hi) {
    uint16_t r;
    asm("cvt.rn.satfinite.e4m3x2.f32 %0, %1, %2;" : "=h"(r) : "f"(hi), "f"(lo));
    return r;
}
__device__ __forceinline__ void cpasync16s(uint32_t saddr, const void* gmem, bool pred) {
    int sz = pred ? 16 : 0;
    asm volatile("cp.async.cg.shared.global [%0], [%1], 16, %2;\n"
                 :: "r"(saddr), "l"(gmem), "r"(sz));
}
__device__ __forceinline__ void mma_fp8(float* d, const uint32_t* a, const uint32_t* b) {
    asm volatile(
        "mma.sync.aligned.m16n8k32.row.col.f32.e4m3.e4m3.f32 "
        "{%0,%1,%2,%3}, {%4,%5,%6,%7}, {%8,%9}, {%0,%1,%2,%3};\n"
        : "+f"(d[0]), "+f"(d[1]), "+f"(d[2]), "+f"(d[3])
        : "r"(a[0]), "r"(a[1]), "r"(a[2]), "r"(a[3]), "r"(b[0]), "r"(b[1]));
}
__device__ __forceinline__ void ldmx4(uint32_t* r, uint32_t saddr) {
    asm volatile("ldmatrix.sync.aligned.m8n8.x4.shared.b16 {%0,%1,%2,%3}, [%4];"
                 : "=r"(r[0]), "=r"(r[1]), "=r"(r[2]), "=r"(r[3]) : "r"(saddr));
}

// ---------------- fp32 -> fp8 conversion, all 4 weight tensors in one launch
__global__ void k_tofp8_all(const float* __restrict__ s0, uint8_t* __restrict__ d0,
                            const float* __restrict__ s1, uint8_t* __restrict__ d1,
                            const float* __restrict__ s2, uint8_t* __restrict__ d2,
                            const float* __restrict__ s3, uint8_t* __restrict__ d3) {
    int blk = blockIdx.x;
    const float* src; uint8_t* dst; long base;
    if (blk < 1536)      { src = s0; dst = d0; base = (long)blk * 1024; }
    else if (blk < 2048) { src = s1; dst = d1; base = (long)(blk - 1536) * 1024; }
    else if (blk < 4096) { src = s2; dst = d2; base = (long)(blk - 2048) * 1024; }
    else                 { src = s3; dst = d3; base = (long)(blk - 4096) * 1024; }
    long i = base + (long)threadIdx.x * 4;
    float4 v = *(const float4*)(src + i);
    uint32_t pk = (uint32_t)pack2fp8(v.x * WSCL, v.y * WSCL)
                | ((uint32_t)pack2fp8(v.z * WSCL, v.w * WSCL) << 16);
    *(uint32_t*)(dst + i) = pk;
}

// ---------------- setup: gather chunked docs + queries, add pos ------------
__global__ void k_setup(const float* __restrict__ qe, const float* __restrict__ de,
                        const float* __restrict__ qm, const float* __restrict__ dm,
                        const float* __restrict__ pq, const float* __restrict__ pd) {
    long gid = (long)blockIdx.x * 256 + threadIdx.x;
    if (gid >= (long)NTOK * EDIM) return;
    int tok = (int)(gid >> 9);
    int e = (int)(gid & 511);
    float val, pos, mk;
    if (tok < QBASE) {
        int s = tok / SCH, t = tok % SCH;
        int b = s / CPD, c = s % CPD;
        int j = c * CHUNK_ + t - OVL;
        if (j >= 0 && j < DLEN) {
            val = de[((long)(b * DLEN + j)) * EDIM + e];
            mk  = dm[b * DLEN + j];
        } else { val = 0.f; mk = 0.f; }
        pos = pd[t * EDIM + e];
    } else {
        int i2 = tok - QBASE; int b = i2 / QLEN, t = i2 % QLEN;
        val = qe[((long)(b * QLEN + t)) * EDIM + e];
        mk  = qm[b * QLEN + t];
        pos = pq[t * EDIM + e];
    }
    g_seq[gid] = val;
    float xv = val + pos;
    g_xb[gid] = __float2bfloat16(xv);
    g_xh[gid] = f2fp8(xv);
    if (e == 0) g_tmask[tok] = mk;
}

// ---------------- fp8 tensor-core GEMM: C[M,N] = A[M,K]@B[N,K]^T -----------
// 128x128 tile, BK=64, 256 threads (8 warps 2x4), warp tile 64x32,
// m16n8k32 e4m3 mma, ldmatrix.x4 loads, double-buffered cp.async,
// register-held global pointers. split-K via gridDim.z. (non-persistent)
__global__ void __launch_bounds__(256, 2) k_gemm_fp8(
    const uint8_t* __restrict__ A, const uint8_t* __restrict__ B,
    const float* __restrict__ Bias, __nv_bfloat16* __restrict__ C16,
    uint8_t* __restrict__ C8, int M, int N, int K, int relu, long zoff)
{
    __shared__ uint8_t As[2][128 * FSTR];
    __shared__ uint8_t Bs[2][128 * FSTR];
    int m0 = blockIdx.y * 128, n0 = blockIdx.x * 128;
    int splits = gridDim.z;
    int Keff = K / splits;
    int kbeg = blockIdx.z * Keff;
    const float* Biasz = (blockIdx.z == 0) ? Bias : nullptr;
    __nv_bfloat16* C16z = C16 ? (C16 + (blockIdx.z ? zoff : 0)) : nullptr;

    int tid = threadIdx.x;
    int warp = tid >> 5, lane = tid & 31;
    int wm = (warp >> 2) * 64, wn = (warp & 3) * 32;
    int gid = lane >> 2, tig = lane & 3;

    float acc[4][4][4];
#pragma unroll
    for (int i = 0; i < 4; i++)
#pragma unroll
        for (int j = 0; j < 4; j++)
#pragma unroll
            for (int r = 0; r < 4; r++) acc[i][j][r] = 0.f;

    int row = tid >> 2;
    int q   = tid & 3;

    bool pm[2], pn[2];
    const uint8_t* aP[2];
    const uint8_t* bP[2];
    uint32_t sA[2][2], sB[2][2];   // [buf][i]
#pragma unroll
    for (int i = 0; i < 2; i++) {
        int r = row + i * 64;
        int gm = m0 + r; pm[i] = gm < M; int gmr = pm[i] ? gm : (M - 1);
        int gn = n0 + r; pn[i] = gn < N; int gnr = pn[i] ? gn : (N - 1);
        aP[i] = A + (long)gmr * K + kbeg + q * 16;
        bP[i] = B + (long)gnr * K + kbeg + q * 16;
#pragma unroll
        for (int b = 0; b < 2; b++) {
            sA[b][i] = (uint32_t)__cvta_generic_to_shared(&As[b][r * FSTR + q * 16]);
            sB[b][i] = (uint32_t)__cvta_generic_to_shared(&Bs[b][r * FSTR + q * 16]);
        }
    }

    int l8 = lane & 7;
    uint32_t aBase[2], bBase[2];
    {
        int aRow = wm + l8 + ((lane & 8) ? 8 : 0);
        uint32_t aOff = (uint32_t)(aRow * FSTR) + ((lane & 16) ? 16u : 0u);
        int bRow = wn + l8 + ((lane & 16) ? 8 : 0);
        uint32_t bOff = (uint32_t)(bRow * FSTR) + ((lane & 8) ? 16u : 0u);
#pragma unroll
        for (int b = 0; b < 2; b++) {
            aBase[b] = (uint32_t)__cvta_generic_to_shared(&As[b][0]) + aOff;
            bBase[b] = (uint32_t)__cvta_generic_to_shared(&Bs[b][0]) + bOff;
        }
    }

    int nk = Keff >> 6;
    {   // prologue: tile 0 -> buf 0
#pragma unroll
        for (int i = 0; i < 2; i++) {
            cpasync16s(sA[0][i], aP[i], pm[i]);
            cpasync16s(sB[0][i], bP[i], pn[i]);
            aP[i] += 64; bP[i] += 64;
        }
        asm volatile("cp.async.commit_group;\n");
    }

    int buf = 0;
    for (int kt = 0; kt < nk; kt++) {
        asm volatile("cp.async.wait_group 0;\n");
        __syncthreads();
        if (kt + 1 < nk) {
            int nb = buf ^ 1;
#pragma unroll
            for (int i = 0; i < 2; i++) {
                cpasync16s(sA[nb][i], aP[i], pm[i]);
                cpasync16s(sB[nb][i], bP[i], pn[i]);
                aP[i] += 64; bP[i] += 64;
            }
            asm volatile("cp.async.commit_group;\n");
        }
#pragma unroll
        for (int ks = 0; ks < 2; ks++) {
            uint32_t koff = (uint32_t)(ks * 32);
            uint32_t af[4][4], bfr[2][4];
#pragma unroll
            for (int mi = 0; mi < 4; mi++)
                ldmx4(af[mi], aBase[buf] + koff + (uint32_t)(mi * 16 * FSTR));
            ldmx4(bfr[0], bBase[buf] + koff);
            ldmx4(bfr[1], bBase[buf] + koff + (uint32_t)(16 * FSTR));
#pragma unroll
            for (int mi = 0; mi < 4; mi++)
#pragma unroll
                for (int ni = 0; ni < 4; ni++)
                    mma_fp8(acc[mi][ni], af[mi], &bfr[ni >> 1][(ni & 1) * 2]);
        }
        buf ^= 1;
        __syncthreads();
    }

#pragma unroll
    for (int mi = 0; mi < 4; mi++) {
        int r0 = m0 + wm + mi * 16 + gid;
        int r1 = r0 + 8;
#pragma unroll
        for (int ni = 0; ni < 4; ni++) {
            int cb = n0 + wn + ni * 8 + 2 * tig;
            float b0 = Biasz ? Biasz[cb] : 0.f;
            float b1 = Biasz ? Biasz[cb + 1] : 0.f;
            float v0 = acc[mi][ni][0] * WSCL_INV + b0, v1 = acc[mi][ni][1] * WSCL_INV + b1;
            float v2 = acc[mi][ni][2] * WSCL_INV + b0, v3 = acc[mi][ni][3] * WSCL_INV + b1;
            if (relu) { v0 = fmaxf(v0, 0.f); v1 = fmaxf(v1, 0.f);
                        v2 = fmaxf(v2, 0.f); v3 = fmaxf(v3, 0.f); }
            if (C16z) {
                if (r0 < M) *(__nv_bfloat162*)(C16z + (long)r0 * N + cb) = __floats2bfloat162_rn(v0, v1);
                if (r1 < M) *(__nv_bfloat162*)(C16z + (long)r1 * N + cb) = __floats2bfloat162_rn(v2, v3);
            }
            if (C8) {
                if (r0 < M) *(uint16_t*)(C8 + (long)r0 * N + cb) = pack2fp8(v0, v1);
                if (r1 < M) *(uint16_t*)(C8 + (long)r1 * N + cb) = pack2fp8(v2, v3);
            }
        }
    }
}

// ---------------- fp32 cos GEMM: 32x64 tile, high occupancy -----------------
// Same per-output K summation order as before (k0 chunks of 16, kk inner).
__global__ void __launch_bounds__(128) k_cos() {
    __shared__ float As[16][32];
    __shared__ float Bs[16][68];
    int b = blockIdx.z;
    int n0 = blockIdx.x * 64;
    const float* A = g_qn + (long)b * QLEN * EDIM;
    const float* B = g_dn + (long)b * DLEN * EDIM;
    float* C = g_cos + (long)b * QLEN * DLEN;
    int tid = threadIdx.x;
    int ty = tid >> 4, tx = tid & 15;   // 8 x 16; micro 4x4
    float acc[4][4];
#pragma unroll
    for (int i = 0; i < 4; i++)
#pragma unroll
        for (int j = 0; j < 4; j++) acc[i][j] = 0.f;

    for (int k0 = 0; k0 < EDIM; k0 += 16) {
        {   // A: 32 rows x 16k = 128 float4, one per thread
            int r = tid >> 2, c = (tid & 3) << 2;
            float4 v = make_float4(0.f, 0.f, 0.f, 0.f);
            if (r < QLEN) v = *(const float4*)(A + (long)r * EDIM + k0 + c);
            As[c + 0][r] = v.x; As[c + 1][r] = v.y; As[c + 2][r] = v.z; As[c + 3][r] = v.w;
        }
#pragma unroll
        for (int j = 0; j < 2; j++) {   // B: 64 rows x 16k = 256 float4
            int idx = tid + 128 * j;
            int r = idx >> 2, c = (idx & 3) << 2;
            int gn = n0 + r;
            float4 v = make_float4(0.f, 0.f, 0.f, 0.f);
            if (gn < DLEN) v = *(const float4*)(B + (long)gn * EDIM + k0 + c);
            Bs[c + 0][r] = v.x; Bs[c + 1][r] = v.y; Bs[c + 2][r] = v.z; Bs[c + 3][r] = v.w;
        }
        __syncthreads();
#pragma unroll
        for (int kk = 0; kk < 16; kk++) {
            float a[4], bb[4];
            *(float4*)(a)  = *(const float4*)(&As[kk][ty * 4]);
            *(float4*)(bb) = *(const float4*)(&Bs[kk][tx * 4]);
#pragma unroll
            for (int i = 0; i < 4; i++)
#pragma unroll
                for (int j = 0; j < 4; j++) acc[i][j] = fmaf(a[i], bb[j], acc[i][j]);
        }
        __syncthreads();
    }
#pragma unroll
    for (int i = 0; i < 4; i++) {
        int m = ty * 4 + i;
        if (m >= QLEN) continue;
#pragma unroll
        for (int j = 0; j < 4; j++) {
            int n = n0 + tx * 4 + j;
            if (n < DLEN) C[(long)m * DLEN + n] = acc[i][j];
        }
    }
}

// ---------------- attention: one block per (sequence, head), 2-row unroll --
__global__ void __launch_bounds__(128) k_attn() {
    int bid = blockIdx.x;
    int s = bid >> 3, h = bid & 7;
    int S, base;
    if (s < NCH) { S = SCH; base = s * SCH; }
    else         { S = QLEN; base = QBASE + (s - NCH) * QLEN; }
    __shared__ float Qs[SCH * HD];
    __shared__ float Kt[HD * 52];
    __shared__ float Vs[SCH * HD];
    __shared__ float mk[52];
    __shared__ float Pw[4][2][52];
    int tid = threadIdx.x;
    for (int idx = tid; idx < S * HD; idx += 128) {
        int r = idx >> 6, d = idx & 63;
        const __nv_bfloat16* row = g_qkvh + (long)(base + r) * (3 * EDIM) + h * HD;
        Qs[idx]        = __bfloat162float(row[d]);
        Kt[d * 52 + r] = __bfloat162float(row[EDIM + d]);
        Vs[idx]        = __bfloat162float(row[2 * EDIM + d]);
    }
    if (tid < S) mk[tid] = g_tmask[base + tid];
    __syncthreads();
    int warp = tid >> 5, lane = tid & 31;
    int j0 = lane, j1 = lane + 32;
    bool v0ok = j0 < S, v1ok;
    for (int i = warp; i < S; i += 8) {
        int ib = i + 4;
        bool has2 = ib < S;
        int ibc = has2 ? ib : i;
        float s0a = -1e30f, s1a = -1e30f, s0b = -1e30f, s1b = -1e30f;
        v1ok = j1 < S;
        if (v0ok) {
            float aa = 0.f, ab = 0.f;
#pragma unroll
            for (int d = 0; d < HD; d++) {
                float kv = Kt[d * 52 + j0];
                aa = fmaf(Qs[i * HD + d], kv, aa);
                ab = fmaf(Qs[ibc * HD + d], kv, ab);
            }
            s0a = (mk[j0] > 0.f) ? aa * 0.125f : -1e9f;
            s0b = (mk[j0] > 0.f) ? ab * 0.125f : -1e9f;
        }
        if (v1ok) {
            float aa = 0.f, ab = 0.f;
#pragma unroll
            for (int d = 0; d < HD; d++) {
                float kv = Kt[d * 52 + j1];
                aa = fmaf(Qs[i * HD + d], kv, aa);
                ab = fmaf(Qs[ibc * HD + d], kv, ab);
            }
            s1a = (mk[j1] > 0.f) ? aa * 0.125f : -1e9f;
            s1b = (mk[j1] > 0.f) ? ab * 0.125f : -1e9f;
        }
        float ma = fmaxf(s0a, s1a);
#pragma unroll
        for (int o = 16; o > 0; o >>= 1) ma = fmaxf(ma, __shfl_xor_sync(0xffffffffu, ma, o));
        float e0a = v0ok ? __expf(s0a - ma) : 0.f;
        float e1a = v1ok ? __expf(s1a - ma) : 0.f;
        float za = e0a + e1a;
#pragma unroll
        for (int o = 16; o > 0; o >>= 1) za += __shfl_xor_sync(0xffffffffu, za, o);
        float inva = 1.f / za;
        if (v0ok) Pw[warp][0][j0] = e0a * inva;
        if (v1ok) Pw[warp][0][j1] = e1a * inva;
        float mb = fmaxf(s0b, s1b);
#pragma unroll
        for (int o = 16; o > 0; o >>= 1) mb = fmaxf(mb, __shfl_xor_sync(0xffffffffu, mb, o));
        float e0b = v0ok ? __expf(s0b - mb) : 0.f;
        float e1b = v1ok ? __expf(s1b - mb) : 0.f;
        float zb = e0b + e1b;
#pragma unroll
        for (int o = 16; o > 0; o >>= 1) zb += __shfl_xor_sync(0xffffffffu, zb, o);
        float invb = 1.f / zb;
        if (v0ok) Pw[warp][1][j0] = e0b * invb;
        if (v1ok) Pw[warp][1][j1] = e1b * invb;
        __syncwarp();
        float o0a = 0.f, o1a = 0.f, o0b = 0.f, o1b = 0.f;
        for (int j = 0; j < S; j++) {
            float pa = Pw[warp][0][j];
            float pb = Pw[warp][1][j];
            float v0 = Vs[j * HD + lane];
            float v1 = Vs[j * HD + lane + 32];
            o0a = fmaf(pa, v0, o0a); o1a = fmaf(pa, v1, o1a);
            o0b = fmaf(pb, v0, o0b); o1b = fmaf(pb, v1, o1b);
        }
        long orow = (long)(base + i) * EDIM + h * HD;
        g_atth[orow + lane]      = f2fp8(o0a);
        g_atth[orow + lane + 32] = f2fp8(o1a);
        if (has2) {
            long orow2 = (long)(base + ib) * EDIM + h * HD;
            g_atth[orow2 + lane]      = f2fp8(o0b);
            g_atth[orow2 + lane + 32] = f2fp8(o1b);
        }
        __syncwarp();
    }
}

// ---------------- residual-add + layernorm ----------------------------------
// finalflag=0: store bf16 + fp8 copies. finalflag=1 (last LN): fuse repnorm.
__global__ void __launch_bounds__(128) k_addln(
    const __nv_bfloat16* __restrict__ X, const __nv_bfloat16* __restrict__ Y,
    const __nv_bfloat16* __restrict__ Y2,
    const float* __restrict__ G, const float* __restrict__ Bv,
    __nv_bfloat16* __restrict__ Out, uint8_t* __restrict__ OutH,
    const float* __restrict__ mixer, int finalflag)
{
    long tok = blockIdx.x;
    int t = threadIdx.x;
    float* dst = nullptr;
    if (finalflag) {
        int tokc = (int)tok;
        if (tokc < QBASE) {
            int s = tokc / SCH, tt = tokc % SCH;
            int tl = tt - OVL;
            if (tl < 0 || tl >= CHUNK_) return;
            int b = s / CPD, c = s % CPD;
            dst = g_dn + ((long)(b * DLEN + c * CHUNK_ + tl)) * EDIM;
        } else {
            dst = g_qn + (long)(tokc - QBASE) * EDIM;
        }
    }
    __nv_bfloat162 x0 = *(const __nv_bfloat162*)(X + tok * EDIM + t * 4);
    __nv_bfloat162 x1 = *(const __nv_bfloat162*)(X + tok * EDIM + t * 4 + 2);
    __nv_bfloat162 y0 = *(const __nv_bfloat162*)(Y + tok * EDIM + t * 4);
    __nv_bfloat162 y1 = *(const __nv_bfloat162*)(Y + tok * EDIM + t * 4 + 2);
    __nv_bfloat162 z0 = *(const __nv_bfloat162*)(Y2 + tok * EDIM + t * 4);
    __nv_bfloat162 z1 = *(const __nv_bfloat162*)(Y2 + tok * EDIM + t * 4 + 2);
    float4 v = make_float4(
        __bfloat162float(x0.x) + __bfloat162float(y0.x) + __bfloat162float(z0.x),
        __bfloat162float(x0.y) + __bfloat162float(y0.y) + __bfloat162float(z0.y),
        __bfloat162float(x1.x) + __bfloat162float(y1.x) + __bfloat162float(z1.x),
        __bfloat162float(x1.y) + __bfloat162float(y1.y) + __bfloat162float(z1.y));
    float s = blockSum128(v.x + v.y + v.z + v.w);
    float mean = s * (1.f / 512.f);
    float dx = v.x - mean, dy = v.y - mean, dz = v.z - mean, dw = v.w - mean;
    float sq = blockSum128(dx * dx + dy * dy + dz * dz + dw * dw);
    float rstd = rsqrtf(sq * (1.f / 512.f) + 1e-5f);
    float4 g = ((const float4*)G)[t], bb = ((const float4*)Bv)[t];
    float4 o = make_float4(dx * rstd * g.x + bb.x, dy * rstd * g.y + bb.y,
                           dz * rstd * g.z + bb.z, dw * rstd * g.w + bb.w);
    if (!finalflag) {
        *(__nv_bfloat162*)(Out + tok * EDIM + t * 4)     = __floats2bfloat162_rn(o.x, o.y);
        *(__nv_bfloat162*)(Out + tok * EDIM + t * 4 + 2) = __floats2bfloat162_rn(o.z, o.w);
        uint32_t pk = (uint32_t)pack2fp8(o.x, o.y) | ((uint32_t)pack2fp8(o.z, o.w) << 16);
        *(uint32_t*)(OutH + tok * EDIM + t * 4) = pk;
        return;
    }
    float mx = mixer[0];
    float mkv = g_tmask[tok];
    float4 sv = ((const float4*)(g_seq + tok * EDIM))[t];
    float4 r = make_float4((mx * sv.x + (1.f - mx) * o.x) * mkv,
                           (mx * sv.y + (1.f - mx) * o.y) * mkv,
                           (mx * sv.z + (1.f - mx) * o.z) * mkv,
                           (mx * sv.w + (1.f - mx) * o.w) * mkv);
    float sq2 = blockSum128(r.x * r.x + r.y * r.y + r.z * r.z + r.w * r.w);
    float inv = 1.f / (sqrtf(sq2) + 1e-13f);
    ((float4*)dst)[t] = make_float4(r.x * inv, r.y * inv, r.z * inv, r.w * inv);
}

// ---------------- per-position validity (m_in * packed) --------------------
__global__ void k_valid(const float* __restrict__ dm) {
    int gid = blockIdx.x * 256 + threadIdx.x;
    if (gid >= NB * DLEN) return;
    int b = gid / DLEN, p = gid % DLEN;
    int c = p / CHUNK_;
    float s = 0.f;
    for (int d = 0; d < CHUNK_; d++) s += dm[b * DLEN + c * CHUNK_ + d];
    float packed = (s != 0.f) ? 1.f : 0.f;
    g_valid[gid] = dm[b * DLEN + p] * packed;
}

// ---------------- RBF kernel activations (bf16 out) --------------------------
__global__ void k_acts(const float* __restrict__ mup, const float* __restrict__ sgp) {
    __shared__ float mu[NKN], i2s[NKN];
    if (threadIdx.x < NKN) {
        mu[threadIdx.x] = mup[threadIdx.x];
        float sg = sgp[threadIdx.x];
        i2s[threadIdx.x] = 1.f / (2.f * sg * sg);
    }
    __syncthreads();
    int gid = blockIdx.x * 256 + threadIdx.x;
    if (gid >= NB * QLEN * DLEN) return;
    int b = gid / (QLEN * DLEN);
    int rem = gid % (QLEN * DLEN);
    int q = rem / DLEN, p = rem % DLEN;
    float c = g_cos[gid];
    float v = g_valid[b * DLEN + p];
#pragma unroll
    for (int k = 0; k < NKN; k++) {
        float d = c - mu[k];
        g_acts[(((long)(b * QLEN + q)) * NKN + k) * DLEN + p] =
            __float2bfloat16(__expf(-d * d * i2s[k]) * v);
    }
}

// ---------------- per-kernel window log-saturation (smem-staged, bf16 src) --
// window validity computed inline from staged g_valid slab (replaces k_wvalid)
__global__ void __launch_bounds__(128) k_perk(const float* __restrict__ qm) {
    __shared__ float sa[QLEN][PERK_POS];
    __shared__ float sv[PERK_POS];
    __shared__ float qms[QLEN];
    int wt = blockIdx.x, k = blockIdx.y, b = blockIdx.z;
    int w0 = wt * 128;
    int p0 = 2 * w0;
    int npos = DLEN - p0; if (npos > PERK_POS) npos = PERK_POS;
    int tid = threadIdx.x;
    for (int idx = tid; idx < QLEN * npos; idx += 128) {
        int q = idx / npos, j = idx % npos;
        sa[q][j] = __bfloat162float(
            g_acts[(((long)(b * QLEN + q)) * NKN + k) * DLEN + p0 + j]);
    }
    for (int j = tid; j < npos; j += 128) sv[j] = g_valid[b * DLEN + p0 + j];
    if (tid < QLEN) qms[tid] = qm[b * QLEN + tid];
    __syncthreads();
    int w = w0 + tid;
    if (w >= WN) return;
    int off = 2 * tid;
    float wv = 0.f;
#pragma unroll
    for (int i = 0; i < 30; i++)
        if (sv[off + i] != 0.f) wv = 1.f;
    float ssum = 0.f;
    if (wv != 0.f) {
        for (int q = 0; q < QLEN; q++) {
            float pkq = 0.f;
#pragma unroll
            for (int i = 0; i < 30; i++) pkq += sa[q][off + i];
            ssum += qms[q] * logf(fmaxf(pkq, 1e-10f));
        }
    }
    g_perk[((long)b * WN + w) * NKN + k] = ssum;
}

// ---------------- score + topk(3) with suppression + neighbor gather --------
__global__ void __launch_bounds__(1024) k_final(
    const float* __restrict__ dw, const float* __restrict__ cs,
    float* __restrict__ out)
{
    int b = blockIdx.x;
    int t = threadIdx.x;
    __shared__ float sc[WN], wk[WN];
    __shared__ float rv[1024];
    __shared__ int   ri[1024];
    __shared__ int   tops[3];
    if (t < WN) {
        const float* pk = g_perk + ((long)b * WN + t) * NKN;
        float s = 0.f;
#pragma unroll
        for (int k = 0; k < NKN; k++) s += pk[k] * dw[k];
        if (s == 0.f) s = -9000.f;
        sc[t] = s; wk[t] = s;
    }
    __syncthreads();
    for (int c = 0; c < 3; c++) {
        rv[t] = (t < WN) ? wk[t] : -1e30f;
        ri[t] = t;
        __syncthreads();
        for (int st = 512; st > 0; st >>= 1) {
            if (t < st) {
                float v2 = rv[t + st]; int i2 = ri[t + st];
                if (v2 > rv[t] || (v2 == rv[t] && i2 < ri[t])) { rv[t] = v2; ri[t] = i2; }
            }
            __syncthreads();
        }
        int best = ri[0];
        if (t == 0) tops[c] = best;
        if (t < WN) {
            int d = t - best; if (d < 0) d = -d;
            if (d < SLIDEH) wk[t] = -10001.f - (float)c;
        }
        __syncthreads();
    }
    if (t == 0) {
        const int offs[5] = {0, -1, 1, -2, 2};
        float acc = 0.f;
        for (int g = 0; g < 5; g++)
            for (int c = 0; c < 3; c++) {
                int n = tops[c] + offs[g];
                n = n < 0 ? 0 : (n > WN - 1 ? WN - 1 : n);
                float v = sc[n];
                if (v <= -9000.f) v = 0.f;
                acc += v * cs[g * 3 + c];
            }
        out[b] = acc;
    }
}

// ---------------- host orchestration ----------------------------------------
static void launch_fp8(const uint8_t* A, const uint8_t* B,
                       const float* bias, __nv_bfloat16* C16, uint8_t* C8,
                       int M, int N, int K, int relu, int splits, long zoff) {
    dim3 grid((N + 127) / 128, (M + 127) / 128, splits);
    k_gemm_fp8<<<grid, 256>>>(A, B, bias, C16, C8, M, N, K, relu, zoff);
}

extern "C" void kernel_launch(void* const* d_in, const int* in_sizes, int n_in,
                              void* d_out, int out_size) {
    (void)in_sizes; (void)n_in; (void)out_size;
    const float* qe   = (const float*)d_in[0];
    const float* de   = (const float*)d_in[1];
    const float* qm   = (const float*)d_in[2];
    const float* dm   = (const float*)d_in[3];
    const float* pq   = (const float*)d_in[4];
    const float* pd   = (const float*)d_in[5];
    const float* Wqkv = (const float*)d_in[6];
    const float* bqkv = (const float*)d_in[7];
    const float* Wo   = (const float*)d_in[8];
    const float* bo   = (const float*)d_in[9];
    const float* ln1g = (const float*)d_in[10];
    const float* ln1b = (const float*)d_in[11];
    const float* Wff1 = (const float*)d_in[12];
    const float* bff1 = (const float*)d_in[13];
    const float* Wff2 = (const float*)d_in[14];
    const float* bff2 = (const float*)d_in[15];
    const float* ln2g = (const float*)d_in[16];
    const float* ln2b = (const float*)d_in[17];
    const float* mixer= (const float*)d_in[18];
    const float* dwp  = (const float*)d_in[19];
    const float* csp  = (const float*)d_in[20];
    const float* mup  = (const float*)d_in[21];
    const float* sgp  = (const float*)d_in[22];
    float* out = (float*)d_out;

    __nv_bfloat16 *p_xb, *p_x1b, *p_qkvh, *p_projh;
    uint8_t *p_xh, *p_x1h, *p_atth, *p_ffh;
    uint8_t *p_wqkvh, *p_woh, *p_wff1h, *p_wff2h;
    cudaGetSymbolAddress((void**)&p_xb,   g_xb);
    cudaGetSymbolAddress((void**)&p_x1b,  g_x1b);
    cudaGetSymbolAddress((void**)&p_qkvh, g_qkvh);
    cudaGetSymbolAddress((void**)&p_projh,g_projh);
    cudaGetSymbolAddress((void**)&p_xh,   g_xh);
    cudaGetSymbolAddress((void**)&p_x1h,  g_x1h);
    cudaGetSymbolAddress((void**)&p_atth, g_atth);
    cudaGetSymbolAddress((void**)&p_ffh,  g_ffh);
    cudaGetSymbolAddress((void**)&p_wqkvh, g_wqkvh);
    cudaGetSymbolAddress((void**)&p_woh,   g_woh);
    cudaGetSymbolAddress((void**)&p_wff1h, g_wff1h);
    cudaGetSymbolAddress((void**)&p_wff2h, g_wff2h);

    const long ZOFF = (long)NTOK * EDIM;
    __nv_bfloat16* p_projh2 = p_projh + ZOFF;

    // launch order: #4 is the first fp8 GEMM (ncu profiles launch #4)
    k_setup<<<(NTOK * EDIM + 255) / 256, 256>>>(qe, de, qm, dm, pq, pd);        // 1
    k_tofp8_all<<<6144, 256>>>(Wqkv, p_wqkvh, Wo, p_woh, Wff1, p_wff1h, Wff2, p_wff2h); // 2
    k_valid<<<(NB * DLEN + 255) / 256, 256>>>(dm);                              // 3

    const uint8_t* xin = p_xh;
    for (int l = 0; l < 2; l++) {
        launch_fp8(xin, p_wqkvh + (long)l * 3 * EDIM * EDIM, bqkv + l * 3 * EDIM,
                   p_qkvh, nullptr, NTOK, 3 * EDIM, EDIM, 0, 1, 0);             // 4 (l=0)
        k_attn<<<NSEQ * HN, 128>>>();
        launch_fp8(p_atth, p_woh + (long)l * EDIM * EDIM, bo + l * EDIM,
                   p_projh, nullptr, NTOK, EDIM, EDIM, 0, 2, ZOFF);
        k_addln<<<NTOK, 128>>>(p_xb, p_projh, p_projh2,
                               ln1g + l * EDIM, ln1b + l * EDIM, p_x1b, p_x1h,
                               mixer, 0);
        launch_fp8(p_x1h, p_wff1h + (long)l * FFD * EDIM, bff1 + l * FFD,
                   nullptr, p_ffh, NTOK, FFD, EDIM, 1, 1, 0);
        launch_fp8(p_ffh, p_wff2h + (long)l * EDIM * FFD, bff2 + l * EDIM,
                   p_projh, nullptr, NTOK, EDIM, FFD, 0, 2, ZOFF);
        k_addln<<<NTOK, 128>>>(p_x1b, p_projh, p_projh2,
                               ln2g + l * EDIM, ln2b + l * EDIM, p_xb, p_xh,
                               mixer, l == 1 ? 1 : 0);
        xin = p_xh;
    }

    {
        dim3 grid((DLEN + 63) / 64, 1, NB);
        k_cos<<<grid, 128>>>();
    }

    k_acts<<<(NB * QLEN * DLEN + 255) / 256, 256>>>(mup, sgp);
    {
        dim3 grid((WN + 127) / 128, NKN, NB);
        k_perk<<<grid, 128>>>(qm);
    }
    k_final <<<NB, 1024>>>(dwp, csp, out);
}